// round 10
// baseline (speedup 1.0000x reference)
#include <cuda_runtime.h>
#include <cuda_bf16.h>
#include <math.h>
#include <stdint.h>

#define BATCH 16
#define CCH   2048
#define HWD   1024
#define DD    256
#define BN_RS 0.9999950000374997f   // 1/sqrt(1 + 1e-5)

// ---------------- scratch (device globals; no allocation) ----------------
__device__ __align__(16) float d_G  [BATCH * DD * DD];   // gram fp32
__device__ float d_invr[BATCH * DD];                     // 1/||rawlat row||
__device__ float d_P1 [BATCH * DD * 64];                 // GEMM1 partial sum-sq
__device__ float d_P2 [BATCH * CCH * 8];                 // GEMM2 partial sum-sq
__device__ float d_invv[BATCH * DD];                     // 1/||psi_v row||
__device__ float d_invz[BATCH * CCH];                    // 1/||psi_l row||

// bf16 hi/lo split operand storage
__device__ __align__(16) __nv_bfloat16 g_v2lh[BATCH*CCH*HWD], g_v2ll[BATCH*CCH*HWD];
__device__ __align__(16) __nv_bfloat16 g_l2vh[BATCH*CCH*HWD], g_l2vl[BATCH*CCH*HWD];
__device__ __align__(16) __nv_bfloat16 g_wvh[DD*HWD], g_wvl[DD*HWD];
__device__ __align__(16) __nv_bfloat16 g_wlh[DD*HWD], g_wll[DD*HWD];
__device__ __align__(16) __nv_bfloat16 g_Eh[BATCH*DD*HWD], g_El[BATCH*DD*HWD];
__device__ __align__(16) __nv_bfloat16 g_Oh[BATCH*DD*HWD], g_Ol[BATCH*DD*HWD];
__device__ __align__(16) __nv_bfloat16 g_Zh[BATCH*CCH*DD], g_Zlo[BATCH*CCH*DD];
__device__ __align__(16) __nv_bfloat16 g_lath[BATCH*DD*HWD], g_latl[BATCH*DD*HWD];
__device__ __align__(16) __nv_bfloat16 g_latTh[BATCH*HWD*DD], g_latTl[BATCH*HWD*DD];
__device__ __align__(16) __nv_bfloat16 g_Gh[BATCH*DD*DD], g_Gl[BATCH*DD*DD];
__device__ __align__(16) __nv_bfloat16 g_l2Th[BATCH*HWD*DD], g_l2Tl[BATCH*HWD*DD];

// ---------------- helpers ----------------
__device__ __forceinline__ uint32_t cvta_s(const void* p){
    return (uint32_t)__cvta_generic_to_shared(p);
}
__device__ __forceinline__ void cpa16(uint32_t d, const void* s){
    asm volatile("cp.async.cg.shared.global [%0], [%1], 16;" :: "r"(d), "l"(s));
}
#define CP_COMMIT() asm volatile("cp.async.commit_group;")
#define CP_WAIT1()  asm volatile("cp.async.wait_group 1;")

#define LDSM4(R, addr) \
    asm volatile("ldmatrix.sync.aligned.m8n8.x4.shared.b16 {%0,%1,%2,%3}, [%4];" \
        : "=r"((R)[0]), "=r"((R)[1]), "=r"((R)[2]), "=r"((R)[3]) : "r"(addr))

#define MMA16816(d, A, b0, b1) \
    asm volatile("mma.sync.aligned.m16n8k16.row.col.f32.bf16.bf16.f32 " \
        "{%0,%1,%2,%3}, {%4,%5,%6,%7}, {%8,%9}, {%0,%1,%2,%3};" \
        : "+f"((d)[0]), "+f"((d)[1]), "+f"((d)[2]), "+f"((d)[3]) \
        : "r"((A)[0]), "r"((A)[1]), "r"((A)[2]), "r"((A)[3]), "r"(b0), "r"(b1))

__device__ __forceinline__ void split16(float4 v, uint2& hi, uint2& lo){
    uint32_t ux = __float_as_uint(v.x), uy = __float_as_uint(v.y);
    uint32_t uz = __float_as_uint(v.z), uw = __float_as_uint(v.w);
    hi.x = __byte_perm(ux, uy, 0x7632);
    hi.y = __byte_perm(uz, uw, 0x7632);
    float lx = v.x - __uint_as_float(ux & 0xFFFF0000u);
    float ly = v.y - __uint_as_float(uy & 0xFFFF0000u);
    float lz = v.z - __uint_as_float(uz & 0xFFFF0000u);
    float lw = v.w - __uint_as_float(uw & 0xFFFF0000u);
    __nv_bfloat162 l01 = __floats2bfloat162_rn(lx, ly);
    __nv_bfloat162 l23 = __floats2bfloat162_rn(lz, lw);
    lo.x = *(uint32_t*)&l01;
    lo.y = *(uint32_t*)&l23;
}
__device__ __forceinline__ uint32_t pack_hi(float x, float y){
    return __byte_perm(__float_as_uint(x), __float_as_uint(y), 0x7632);
}
__device__ __forceinline__ uint32_t pack_lo(float x, float y){
    float lx = x - __uint_as_float(__float_as_uint(x) & 0xFFFF0000u);
    float ly = y - __uint_as_float(__float_as_uint(y) & 0xFFFF0000u);
    __nv_bfloat162 p = __floats2bfloat162_rn(lx, ly);
    return *(uint32_t*)&p;
}
__device__ __forceinline__ void store_hl(__nv_bfloat16* H, __nv_bfloat16* L, long i, float v){
    uint32_t u = __float_as_uint(v);
    ((unsigned short*)H)[i] = (unsigned short)(u >> 16);
    float r = v - __uint_as_float(u & 0xFFFF0000u);
    L[i] = __float2bfloat16(r);
}

// ---------------- bf16 hi/lo NT GEMM, cp.async pipelined, 2 CTA/SM --------
// D[m,n] = sum_p sum_k A_p[m,k]*B_p[n,k], 3 bf16 passes (hh + hl + lh)
// EPI: 0 fp32 out; 3 split-bf16 out; 4 fp32 out scaled by gs[b*CCH+m];
//      5 (psi_v): BN+ReLU + deinterleave-split E/O out + row sumsq partials
//      6 (psi_l): BN+ReLU(col) + split out + row sumsq partials
struct GArgs {
    const __nv_bfloat16 *A0h, *A0l, *B0h, *B0l;
    const __nv_bfloat16 *A1h, *A1l, *B1h, *B1l;
    void *C, *C2, *C3, *C4;
    float *P;
    const float *gs, *bs;
    long sA, sB, sC;
    int lda, ldb, ldc, K;
};

#define STG3   32768
#define G_SMEM (3 * STG3)

template<int EPI, int NP>
__global__ void __launch_bounds__(256, 2) mma_gemm(GArgs a)
{
    extern __shared__ __align__(128) char smem[];
    const int tid = threadIdx.x, w = tid >> 5, lane = tid & 31;
    const int bn0 = blockIdx.x << 7, bm0 = blockIdx.y << 7, b = blockIdx.z;
    const int KS = a.K >> 5;
    const int NS = KS * NP;
    const uint32_t sbase = cvta_s(smem);
    const int wm = w >> 2, wn = w & 3;

    const int r0 = tid >> 2, ch = tid & 3;
    const uint32_t q16 = (uint32_t)((ch ^ ((r0 >> 1) & 3)) * 16);

    auto issue = [&](int s){
        if (s >= NS) return;
        int p = (NP == 2 && s >= KS) ? 1 : 0;
        long k0 = (long)(s - p * KS) * 32;
        const __nv_bfloat16* srcs[4] = {
            (p ? a.A1h : a.A0h) + (long)b * a.sA + (long)bm0 * a.lda + k0,
            (p ? a.A1l : a.A0l) + (long)b * a.sA + (long)bm0 * a.lda + k0,
            (p ? a.B1h : a.B0h) + (long)b * a.sB + (long)bn0 * a.ldb + k0,
            (p ? a.B1l : a.B0l) + (long)b * a.sB + (long)bn0 * a.ldb + k0
        };
        uint32_t dst0 = sbase + (uint32_t)(s % 3) * STG3 + (uint32_t)r0 * 64u + q16;
        #pragma unroll
        for (int sub = 0; sub < 4; sub++){
            long ld = (sub < 2) ? a.lda : a.ldb;
            const __nv_bfloat16* sp = srcs[sub] + (long)r0 * ld + ch * 8;
            cpa16(dst0 + sub * 8192,        sp);
            cpa16(dst0 + sub * 8192 + 4096, sp + 64 * ld);
        }
    };

    float acc[4][4][4];
    #pragma unroll
    for (int i = 0; i < 4; i++)
        #pragma unroll
        for (int j = 0; j < 4; j++)
            #pragma unroll
            for (int t = 0; t < 4; t++) acc[i][j][t] = 0.0f;

    const int aRow = wm * 64 + (lane & 15);
    const uint32_t lqA = (uint32_t)(((lane & 15) >> 1) & 3);
    const uint32_t aC0 = (uint32_t)(lane >> 4);
    const int bRow = wn * 32 + (lane & 7) + ((lane >> 4) & 1) * 8;
    const uint32_t lqB = (uint32_t)(((lane & 7) >> 1) & 3);
    const uint32_t bC0 = (uint32_t)((lane >> 3) & 1);

    issue(0); CP_COMMIT();
    issue(1); CP_COMMIT();

    for (int i = 0; i < NS; i++){
        CP_WAIT1();
        __syncthreads();
        issue(i + 2);
        CP_COMMIT();

        const uint32_t stb = sbase + (uint32_t)(i % 3) * STG3;
        #pragma unroll
        for (int ks = 0; ks < 2; ks++){
            const uint32_t qa = ((aC0 + 2 * ks) ^ lqA) * 16u;
            const uint32_t qb = ((bC0 + 2 * ks) ^ lqB) * 16u;
            uint32_t Afh[4][4], Bfh[2][4], Bfl[2][4];
            #pragma unroll
            for (int mi = 0; mi < 4; mi++){
                uint32_t ad = stb + (uint32_t)(aRow + mi * 16) * 64u + qa;
                LDSM4(Afh[mi], ad);
            }
            #pragma unroll
            for (int nb = 0; nb < 2; nb++){
                uint32_t bd = stb + 16384u + (uint32_t)(bRow + nb * 16) * 64u + qb;
                LDSM4(Bfh[nb], bd);
                LDSM4(Bfl[nb], bd + 8192);
            }
            #pragma unroll
            for (int mi = 0; mi < 4; mi++)
                #pragma unroll
                for (int ni = 0; ni < 4; ni++){
                    int nb = ni >> 1, h = (ni & 1) * 2;
                    MMA16816(acc[mi][ni], Afh[mi], Bfh[nb][h], Bfh[nb][h + 1]);
                }
            #pragma unroll
            for (int mi = 0; mi < 4; mi++)
                #pragma unroll
                for (int ni = 0; ni < 4; ni++){
                    int nb = ni >> 1, h = (ni & 1) * 2;
                    MMA16816(acc[mi][ni], Afh[mi], Bfl[nb][h], Bfl[nb][h + 1]);
                }
            uint32_t Afl[4][4];
            #pragma unroll
            for (int mi = 0; mi < 4; mi++){
                uint32_t ad = stb + 8192u + (uint32_t)(aRow + mi * 16) * 64u + qa;
                LDSM4(Afl[mi], ad);
            }
            #pragma unroll
            for (int mi = 0; mi < 4; mi++)
                #pragma unroll
                for (int ni = 0; ni < 4; ni++){
                    int nb = ni >> 1, h = (ni & 1) * 2;
                    MMA16816(acc[mi][ni], Afl[mi], Bfh[nb][h], Bfh[nb][h + 1]);
                }
        }
    }

    // ---- epilogue
    const int r1 = lane >> 2, cq = (lane & 3) * 2;
    if (EPI == 3){
        __nv_bfloat16* Ch = (__nv_bfloat16*)a.C;
        __nv_bfloat16* Cl = (__nv_bfloat16*)a.C2;
        const long cb = (long)b * a.sC;
        #pragma unroll
        for (int mi = 0; mi < 4; mi++){
            int m0 = bm0 + wm * 64 + mi * 16 + r1;
            #pragma unroll
            for (int ni = 0; ni < 4; ni++){
                int n = bn0 + wn * 32 + ni * 8 + cq;
                float v0 = acc[mi][ni][0], v1 = acc[mi][ni][1];
                float v2 = acc[mi][ni][2], v3 = acc[mi][ni][3];
                *(uint32_t*)(Ch + cb + (long)m0 * a.ldc + n)       = pack_hi(v0, v1);
                *(uint32_t*)(Cl + cb + (long)m0 * a.ldc + n)       = pack_lo(v0, v1);
                *(uint32_t*)(Ch + cb + (long)(m0 + 8) * a.ldc + n) = pack_hi(v2, v3);
                *(uint32_t*)(Cl + cb + (long)(m0 + 8) * a.ldc + n) = pack_lo(v2, v3);
            }
        }
    } else if (EPI == 5){
        __nv_bfloat16 *Ehp = (__nv_bfloat16*)a.C,  *Elp = (__nv_bfloat16*)a.C2;
        __nv_bfloat16 *Ohp = (__nv_bfloat16*)a.C3, *Olp = (__nv_bfloat16*)a.C4;
        #pragma unroll
        for (int mi = 0; mi < 4; mi++){
            int m0 = bm0 + wm * 64 + mi * 16 + r1;
            float s0 = a.gs[m0] * BN_RS,     b0_ = a.bs[m0];
            float s1 = a.gs[m0 + 8] * BN_RS, b1_ = a.bs[m0 + 8];
            float sq0 = 0.f, sq1 = 0.f;
            #pragma unroll
            for (int ni = 0; ni < 4; ni++){
                int n = bn0 + wn * 32 + ni * 8 + cq;  // even col
                long ci = n >> 1;
                float v0 = fmaxf(fmaf(acc[mi][ni][0], s0, b0_), 0.f);
                float v1 = fmaxf(fmaf(acc[mi][ni][1], s0, b0_), 0.f);
                float v2 = fmaxf(fmaf(acc[mi][ni][2], s1, b1_), 0.f);
                float v3 = fmaxf(fmaf(acc[mi][ni][3], s1, b1_), 0.f);
                sq0 += v0 * v0 + v1 * v1;
                sq1 += v2 * v2 + v3 * v3;
                long i0 = ((long)b * DD + m0) * HWD + ci;
                long i1 = ((long)b * DD + m0 + 8) * HWD + ci;
                store_hl(Ehp, Elp, i0, v0);
                store_hl(Ohp, Olp, i0, v1);
                store_hl(Ehp, Elp, i1, v2);
                store_hl(Ohp, Olp, i1, v3);
            }
            sq0 += __shfl_xor_sync(0xffffffffu, sq0, 1);
            sq0 += __shfl_xor_sync(0xffffffffu, sq0, 2);
            sq1 += __shfl_xor_sync(0xffffffffu, sq1, 1);
            sq1 += __shfl_xor_sync(0xffffffffu, sq1, 2);
            if ((lane & 3) == 0){
                a.P[(((long)b * DD + m0) * 16 + blockIdx.x) * 4 + wn]     = sq0;
                a.P[(((long)b * DD + m0 + 8) * 16 + blockIdx.x) * 4 + wn] = sq1;
            }
        }
    } else if (EPI == 6){
        __nv_bfloat16* Ch = (__nv_bfloat16*)a.C;
        __nv_bfloat16* Cl = (__nv_bfloat16*)a.C2;
        const long cb = (long)b * a.sC;
        #pragma unroll
        for (int mi = 0; mi < 4; mi++){
            int m0 = bm0 + wm * 64 + mi * 16 + r1;
            float sq0 = 0.f, sq1 = 0.f;
            #pragma unroll
            for (int ni = 0; ni < 4; ni++){
                int n = bn0 + wn * 32 + ni * 8 + cq;
                float gs0 = a.gs[n] * BN_RS, bb0 = a.bs[n];
                float gs1 = a.gs[n + 1] * BN_RS, bb1 = a.bs[n + 1];
                float v0 = fmaxf(fmaf(acc[mi][ni][0], gs0, bb0), 0.f);
                float v1 = fmaxf(fmaf(acc[mi][ni][1], gs1, bb1), 0.f);
                float v2 = fmaxf(fmaf(acc[mi][ni][2], gs0, bb0), 0.f);
                float v3 = fmaxf(fmaf(acc[mi][ni][3], gs1, bb1), 0.f);
                sq0 += v0 * v0 + v1 * v1;
                sq1 += v2 * v2 + v3 * v3;
                *(uint32_t*)(Ch + cb + (long)m0 * a.ldc + n)       = pack_hi(v0, v1);
                *(uint32_t*)(Cl + cb + (long)m0 * a.ldc + n)       = pack_lo(v0, v1);
                *(uint32_t*)(Ch + cb + (long)(m0 + 8) * a.ldc + n) = pack_hi(v2, v3);
                *(uint32_t*)(Cl + cb + (long)(m0 + 8) * a.ldc + n) = pack_lo(v2, v3);
            }
            sq0 += __shfl_xor_sync(0xffffffffu, sq0, 1);
            sq0 += __shfl_xor_sync(0xffffffffu, sq0, 2);
            sq1 += __shfl_xor_sync(0xffffffffu, sq1, 1);
            sq1 += __shfl_xor_sync(0xffffffffu, sq1, 2);
            if ((lane & 3) == 0){
                int pc = (bn0 >> 7) * 4 + wn;
                a.P[((long)b * CCH + m0) * 8 + pc]     = sq0;
                a.P[((long)b * CCH + m0 + 8) * 8 + pc] = sq1;
            }
        }
    } else {  // EPI 0 or 4
        float* Cb = (float*)a.C + (long)b * a.sC;
        #pragma unroll
        for (int mi = 0; mi < 4; mi++){
            int m0 = bm0 + wm * 64 + mi * 16 + r1;
            float rz0 = 1.f, rz1 = 1.f;
            if (EPI == 4){
                rz0 = a.gs[(long)b * CCH + m0];
                rz1 = a.gs[(long)b * CCH + m0 + 8];
            }
            #pragma unroll
            for (int ni = 0; ni < 4; ni++){
                int n = bn0 + wn * 32 + ni * 8 + cq;
                float v0 = acc[mi][ni][0] * rz0, v1 = acc[mi][ni][1] * rz0;
                float v2 = acc[mi][ni][2] * rz1, v3 = acc[mi][ni][3] * rz1;
                *(float2*)(Cb + (long)m0 * a.ldc + n)       = make_float2(v0, v1);
                *(float2*)(Cb + (long)(m0 + 8) * a.ldc + n) = make_float2(v2, v3);
            }
        }
    }
}

// ---------------- reductions ----------------
__device__ __forceinline__ float warpSum(float v){
    #pragma unroll
    for (int o = 16; o; o >>= 1) v += __shfl_xor_sync(0xffffffffu, v, o);
    return v;
}
__device__ __forceinline__ float warpMax(float v){
    #pragma unroll
    for (int o = 16; o; o >>= 1) v = fmaxf(v, __shfl_xor_sync(0xffffffffu, v, o));
    return v;
}
__device__ __forceinline__ float blockSum(float v){
    __shared__ float sh[32];
    int w = threadIdx.x >> 5, l = threadIdx.x & 31;
    v = warpSum(v);
    if (l == 0) sh[w] = v;
    __syncthreads();
    int nw = blockDim.x >> 5;
    if (w == 0){ float x = (l < nw) ? sh[l] : 0.0f; x = warpSum(x); if (l == 0) sh[0] = x; }
    __syncthreads();
    float r = sh[0];
    __syncthreads();
    return r;
}
__device__ __forceinline__ float blockMax(float v){
    __shared__ float sh[32];
    int w = threadIdx.x >> 5, l = threadIdx.x & 31;
    v = warpMax(v);
    if (l == 0) sh[w] = v;
    __syncthreads();
    int nw = blockDim.x >> 5;
    if (w == 0){ float x = (l < nw) ? sh[l] : -INFINITY; x = warpMax(x); if (l == 0) sh[0] = x; }
    __syncthreads();
    float r = sh[0];
    __syncthreads();
    return r;
}

// ---------------- elementwise kernels ----------------
__global__ void __launch_bounds__(256)
k_split(const float4* __restrict__ in, uint2* __restrict__ hi, uint2* __restrict__ lo, int n4)
{
    int i = blockIdx.x * blockDim.x + threadIdx.x;
    int stride = gridDim.x * blockDim.x;
    for (; i < n4; i += stride){
        float4 v = in[i];
        uint2 h, l;
        split16(v, h, l);
        hi[i] = h;
        lo[i] = l;
    }
}

// reduce partial sum-squares -> inverse norms
__global__ void __launch_bounds__(256)
k_rinv(const float* __restrict__ P, float* __restrict__ R, int cnt, int rows)
{
    int row = blockIdx.x * blockDim.x + threadIdx.x;
    if (row >= rows) return;
    const float* p = P + (long)row * cnt;
    float s = 0.0f;
    for (int i = 0; i < cnt; i++) s += p[i];
    R[row] = 1.0f / fmaxf(sqrtf(s), 1e-12f);
}

// transpose lat_hi/lo [b,256,1024] -> latT_hi/lo [b,1024,256]
__global__ void __launch_bounds__(256)
k_transpose(const uint32_t* __restrict__ sH, const uint32_t* __restrict__ sL,
            uint32_t* __restrict__ dH, uint32_t* __restrict__ dL)
{
    __shared__ unsigned short tile[32][34];
    const int b = blockIdx.z, h0 = blockIdx.x * 32, d0 = blockIdx.y * 32;
    const int t = threadIdx.x;
    const uint32_t* srcs[2] = {sH, sL};
    uint32_t* dsts[2] = {dH, dL};
    #pragma unroll
    for (int m = 0; m < 2; m++){
        #pragma unroll
        for (int i = 0; i < 2; i++){
            int s = t + i * 256;
            int d = s >> 4, hu = s & 15;
            uint32_t v = srcs[m][(long)(b * 256 + d0 + d) * 512 + (h0 >> 1) + hu];
            tile[d][2 * hu]     = (unsigned short)(v & 0xFFFFu);
            tile[d][2 * hu + 1] = (unsigned short)(v >> 16);
        }
        __syncthreads();
        #pragma unroll
        for (int i = 0; i < 2; i++){
            int s = t + i * 256;
            int h = s >> 4, du = s & 15;
            uint32_t v = (uint32_t)tile[2 * du][h] | ((uint32_t)tile[2 * du + 1][h] << 16);
            dsts[m][(long)(b * 1024 + h0 + h) * 128 + (d0 >> 1) + du] = v;
        }
        __syncthreads();
    }
}

// latent row inverse norms from hi/lo (raw lat)
__global__ void __launch_bounds__(256)
k_latnorm(const uint32_t* __restrict__ H, const uint32_t* __restrict__ L, float* __restrict__ R)
{
    long row = blockIdx.x;
    long base = row * 512;
    int t = threadIdx.x;
    float s = 0.0f;
    #pragma unroll
    for (int i = 0; i < 2; i++){
        long idx = base + t + i * 256;
        uint32_t uh = H[idx], ul = L[idx];
        float2 fh = __bfloat1622float2(*(__nv_bfloat162*)&uh);
        float2 fl = __bfloat1622float2(*(__nv_bfloat162*)&ul);
        float v0 = fh.x + fl.x, v1 = fh.y + fl.y;
        s += v0 * v0 + v1 * v1;
    }
    s = blockSum(s);
    if (t == 0) R[row] = 1.0f / fmaxf(sqrtf(s), 1e-12f);
}

// softmax over scaled gram rows; fold invv column scale; write split bf16
__global__ void __launch_bounds__(256)
k_softmax(const float* __restrict__ G, const float* __restrict__ R,
          const float* __restrict__ IV,
          uint32_t* __restrict__ Gh, uint32_t* __restrict__ Gl)
{
    long row = blockIdx.x;
    long bb = row >> 8;
    int t = threadIdx.x;
    float ri = R[row];
    float re = R[(bb << 8) + t];
    float x = G[row * 256 + t] * ri * re;
    float mx = blockMax(x);
    float p = expf(x - mx);
    float sm = blockSum(p);
    float g = (p / sm) * IV[(bb << 8) + t];   // fold psi_v inverse norm (column e)
    float gn = __shfl_down_sync(0xffffffffu, g, 1);
    if ((t & 1) == 0){
        Gh[row * 128 + (t >> 1)] = pack_hi(g, gn);
        Gl[row * 128 + (t >> 1)] = pack_lo(g, gn);
    }
}

// ---------------- launch ----------------
extern "C" void kernel_launch(void* const* d_in, const int* in_sizes, int n_in,
                              void* d_out, int out_size)
{
    const float* v2l = (const float*)d_in[0];
    const float* l2v = (const float*)d_in[1];
    const float* wv  = (const float*)d_in[2];
    const float* gv  = (const float*)d_in[3];
    const float* bv  = (const float*)d_in[4];
    const float* wl  = (const float*)d_in[5];
    const float* gl  = (const float*)d_in[6];
    const float* bl  = (const float*)d_in[7];
    float* out = (float*)d_out;

    float *G, *invr, *P1, *P2, *invv, *invz;
    __nv_bfloat16 *v2lh, *v2ll, *l2vh, *l2vl, *wvh, *wvl, *wlh, *wll;
    __nv_bfloat16 *Eh, *El, *Oh, *Ol, *Zh, *Zlo, *lath, *latl, *latTh, *latTl;
    __nv_bfloat16 *Ghb, *Glb, *l2Th, *l2Tl;
    cudaGetSymbolAddress((void**)&G, d_G);
    cudaGetSymbolAddress((void**)&invr, d_invr);
    cudaGetSymbolAddress((void**)&P1, d_P1);
    cudaGetSymbolAddress((void**)&P2, d_P2);
    cudaGetSymbolAddress((void**)&invv, d_invv);
    cudaGetSymbolAddress((void**)&invz, d_invz);
    cudaGetSymbolAddress((void**)&v2lh, g_v2lh); cudaGetSymbolAddress((void**)&v2ll, g_v2ll);
    cudaGetSymbolAddress((void**)&l2vh, g_l2vh); cudaGetSymbolAddress((void**)&l2vl, g_l2vl);
    cudaGetSymbolAddress((void**)&wvh, g_wvh);   cudaGetSymbolAddress((void**)&wvl, g_wvl);
    cudaGetSymbolAddress((void**)&wlh, g_wlh);   cudaGetSymbolAddress((void**)&wll, g_wll);
    cudaGetSymbolAddress((void**)&Eh, g_Eh);     cudaGetSymbolAddress((void**)&El, g_El);
    cudaGetSymbolAddress((void**)&Oh, g_Oh);     cudaGetSymbolAddress((void**)&Ol, g_Ol);
    cudaGetSymbolAddress((void**)&Zh, g_Zh);     cudaGetSymbolAddress((void**)&Zlo, g_Zlo);
    cudaGetSymbolAddress((void**)&lath, g_lath); cudaGetSymbolAddress((void**)&latl, g_latl);
    cudaGetSymbolAddress((void**)&latTh, g_latTh); cudaGetSymbolAddress((void**)&latTl, g_latTl);
    cudaGetSymbolAddress((void**)&Ghb, g_Gh);    cudaGetSymbolAddress((void**)&Glb, g_Gl);
    cudaGetSymbolAddress((void**)&l2Th, g_l2Th); cudaGetSymbolAddress((void**)&l2Tl, g_l2Tl);

    cudaFuncSetAttribute(mma_gemm<0,1>, cudaFuncAttributeMaxDynamicSharedMemorySize, G_SMEM);
    cudaFuncSetAttribute(mma_gemm<3,1>, cudaFuncAttributeMaxDynamicSharedMemorySize, G_SMEM);
    cudaFuncSetAttribute(mma_gemm<3,2>, cudaFuncAttributeMaxDynamicSharedMemorySize, G_SMEM);
    cudaFuncSetAttribute(mma_gemm<4,1>, cudaFuncAttributeMaxDynamicSharedMemorySize, G_SMEM);
    cudaFuncSetAttribute(mma_gemm<5,1>, cudaFuncAttributeMaxDynamicSharedMemorySize, G_SMEM);
    cudaFuncSetAttribute(mma_gemm<6,1>, cudaFuncAttributeMaxDynamicSharedMemorySize, G_SMEM);

    const long FEAT = (long)CCH * HWD;
    dim3 blk(256);

    // 0) splits of raw inputs + weights
    k_split<<<8192, blk>>>((const float4*)v2l, (uint2*)v2lh, (uint2*)v2ll, (int)(BATCH*FEAT/4));
    k_split<<<8192, blk>>>((const float4*)l2v, (uint2*)l2vh, (uint2*)l2vl, (int)(BATCH*FEAT/4));
    k_split<<<256, blk>>>((const float4*)wv, (uint2*)wvh, (uint2*)wvl, DD*HWD/4);
    k_split<<<256, blk>>>((const float4*)wl, (uint2*)wlh, (uint2*)wll, DD*HWD/4);

    // 1) psi_v: raw BN+ReLU, deinterleave-split to E/O + sumsq partials
    {
        GArgs a = { wvh, wvl, v2lh, v2ll, nullptr, nullptr, nullptr, nullptr,
                    Eh, El, Oh, Ol, P1, gv, bv,
                    0, FEAT, 0, HWD, HWD, 0, HWD };
        mma_gemm<5,1><<<dim3(CCH/128, DD/128, BATCH), blk, G_SMEM>>>(a);
    }
    // 1b) invv = 1/||psi_v row||
    k_rinv<<<(BATCH*DD + 255)/256, blk>>>(P1, invv, 64, BATCH*DD);

    // 2) psi_l: raw BN+ReLU, split Zh/Zlo + sumsq partials
    {
        GArgs a = { l2vh, l2vl, wlh, wll, nullptr, nullptr, nullptr, nullptr,
                    Zh, Zlo, nullptr, nullptr, P2, gl, bl,
                    FEAT, 0, (long)CCH*DD, HWD, HWD, DD, HWD };
        mma_gemm<6,1><<<dim3(DD/128, CCH/128, BATCH), blk, G_SMEM>>>(a);
    }
    // 2b) invz = 1/||psi_l row||
    k_rinv<<<(BATCH*CCH + 255)/256, blk>>>(P2, invz, 8, BATCH*CCH);

    // 5) rawlat = Yv_even.Vlow^T + Yv_odd.Vhigh^T  -> split bf16
    {
        GArgs a = { Eh, El, v2lh, v2ll, Oh, Ol, v2lh + (long)HWD*HWD, v2ll + (long)HWD*HWD,
                    lath, latl, nullptr, nullptr, nullptr, nullptr, nullptr,
                    (long)DD*HWD, FEAT, (long)DD*HWD, HWD, HWD, HWD, HWD };
        mma_gemm<3,2><<<dim3(HWD/128, DD/128, BATCH), blk, G_SMEM>>>(a);
    }
    // 6) transpose rawlat -> latT
    k_transpose<<<dim3(32, 8, BATCH), blk>>>(
        (const uint32_t*)lath, (const uint32_t*)latl, (uint32_t*)latTh, (uint32_t*)latTl);
    // 7) rawlat row inverse norms
    k_latnorm<<<BATCH*DD, blk>>>((const uint32_t*)lath, (const uint32_t*)latl, invr);
    // 8) G = rawlat . rawlat^T (fp32)
    {
        GArgs a = { lath, latl, lath, latl, nullptr, nullptr, nullptr, nullptr,
                    G, nullptr, nullptr, nullptr, nullptr, nullptr, nullptr,
                    (long)DD*HWD, (long)DD*HWD, (long)DD*DD, HWD, HWD, DD, HWD };
        mma_gemm<0,1><<<dim3(DD/128, DD/128, BATCH), blk, G_SMEM>>>(a);
    }
    // 9) aff' = softmax(G·ri·re) * invv[e]  -> split bf16
    k_softmax<<<BATCH*DD, blk>>>(G, invr, invv, (uint32_t*)Ghb, (uint32_t*)Glb);
    // 10) l2T = latT . aff'^T  -> split bf16
    {
        GArgs a = { latTh, latTl, Ghb, Glb, nullptr, nullptr, nullptr, nullptr,
                    l2Th, l2Tl, nullptr, nullptr, nullptr, nullptr, nullptr,
                    (long)HWD*DD, (long)DD*DD, (long)HWD*DD, DD, DD, DD, DD };
        mma_gemm<3,1><<<dim3(DD/128, HWD/128, BATCH), blk, G_SMEM>>>(a);
    }
    // 11) out = (Z . l2T^T) * invz[c]  (fp32 out)
    {
        GArgs a = { Zh, Zlo, l2Th, l2Tl, nullptr, nullptr, nullptr, nullptr,
                    out, nullptr, nullptr, nullptr, nullptr, invz, nullptr,
                    (long)CCH*DD, (long)HWD*DD, (long)CCH*HWD, DD, DD, HWD, DD };
        mma_gemm<4,1><<<dim3(HWD/128, CCH/128, BATCH), blk, G_SMEM>>>(a);
    }
}

// round 11
// speedup vs baseline: 1.0026x; 1.0026x over previous
#include <cuda_runtime.h>
#include <cuda_bf16.h>
#include <math.h>
#include <stdint.h>

#define BATCH 16
#define CCH   2048
#define HWD   1024
#define DD    256
#define BN_RS 0.9999950000374997f   // 1/sqrt(1 + 1e-5)

// ---------------- scratch (device globals; no allocation) ----------------
__device__ __align__(16) float d_G  [BATCH * DD * DD];   // gram fp32
__device__ float d_invr[BATCH * DD];                     // 1/||rawlat row||
__device__ float d_P1 [BATCH * DD * 64];                 // GEMM1 partial sum-sq
__device__ float d_P2 [BATCH * CCH * 8];                 // GEMM2 partial sum-sq
__device__ float d_invv[BATCH * DD];                     // 1/||psi_v row||
__device__ float d_invz[BATCH * CCH];                    // 1/||psi_l row||

// bf16 hi/lo split operand storage
__device__ __align__(16) __nv_bfloat16 g_v2lh[BATCH*CCH*HWD], g_v2ll[BATCH*CCH*HWD];
__device__ __align__(16) __nv_bfloat16 g_l2vh[BATCH*CCH*HWD], g_l2vl[BATCH*CCH*HWD];
__device__ __align__(16) __nv_bfloat16 g_wvh[DD*HWD], g_wvl[DD*HWD];
__device__ __align__(16) __nv_bfloat16 g_wlh[DD*HWD], g_wll[DD*HWD];
__device__ __align__(16) __nv_bfloat16 g_Eh[BATCH*DD*HWD], g_El[BATCH*DD*HWD];
__device__ __align__(16) __nv_bfloat16 g_Oh[BATCH*DD*HWD], g_Ol[BATCH*DD*HWD];
__device__ __align__(16) __nv_bfloat16 g_Zh[BATCH*CCH*DD], g_Zlo[BATCH*CCH*DD];
__device__ __align__(16) __nv_bfloat16 g_lath[BATCH*DD*HWD], g_latl[BATCH*DD*HWD];
__device__ __align__(16) __nv_bfloat16 g_latTh[BATCH*HWD*DD], g_latTl[BATCH*HWD*DD];
__device__ __align__(16) __nv_bfloat16 g_Gh[BATCH*DD*DD], g_Gl[BATCH*DD*DD];
__device__ __align__(16) __nv_bfloat16 g_l2Th[BATCH*HWD*DD], g_l2Tl[BATCH*HWD*DD];

// ---------------- helpers ----------------
__device__ __forceinline__ uint32_t cvta_s(const void* p){
    return (uint32_t)__cvta_generic_to_shared(p);
}
__device__ __forceinline__ void cpa16(uint32_t d, const void* s){
    asm volatile("cp.async.cg.shared.global [%0], [%1], 16;" :: "r"(d), "l"(s));
}
#define CP_COMMIT() asm volatile("cp.async.commit_group;")
#define CP_WAIT1()  asm volatile("cp.async.wait_group 1;")

#define LDSM4(R, addr) \
    asm volatile("ldmatrix.sync.aligned.m8n8.x4.shared.b16 {%0,%1,%2,%3}, [%4];" \
        : "=r"((R)[0]), "=r"((R)[1]), "=r"((R)[2]), "=r"((R)[3]) : "r"(addr))

#define MMA16816(d, A, b0, b1) \
    asm volatile("mma.sync.aligned.m16n8k16.row.col.f32.bf16.bf16.f32 " \
        "{%0,%1,%2,%3}, {%4,%5,%6,%7}, {%8,%9}, {%0,%1,%2,%3};" \
        : "+f"((d)[0]), "+f"((d)[1]), "+f"((d)[2]), "+f"((d)[3]) \
        : "r"((A)[0]), "r"((A)[1]), "r"((A)[2]), "r"((A)[3]), "r"(b0), "r"(b1))

__device__ __forceinline__ void split16(float4 v, uint2& hi, uint2& lo){
    uint32_t ux = __float_as_uint(v.x), uy = __float_as_uint(v.y);
    uint32_t uz = __float_as_uint(v.z), uw = __float_as_uint(v.w);
    hi.x = __byte_perm(ux, uy, 0x7632);
    hi.y = __byte_perm(uz, uw, 0x7632);
    float lx = v.x - __uint_as_float(ux & 0xFFFF0000u);
    float ly = v.y - __uint_as_float(uy & 0xFFFF0000u);
    float lz = v.z - __uint_as_float(uz & 0xFFFF0000u);
    float lw = v.w - __uint_as_float(uw & 0xFFFF0000u);
    __nv_bfloat162 l01 = __floats2bfloat162_rn(lx, ly);
    __nv_bfloat162 l23 = __floats2bfloat162_rn(lz, lw);
    lo.x = *(uint32_t*)&l01;
    lo.y = *(uint32_t*)&l23;
}
__device__ __forceinline__ uint32_t pack_hi(float x, float y){
    return __byte_perm(__float_as_uint(x), __float_as_uint(y), 0x7632);
}
__device__ __forceinline__ uint32_t pack_lo(float x, float y){
    float lx = x - __uint_as_float(__float_as_uint(x) & 0xFFFF0000u);
    float ly = y - __uint_as_float(__float_as_uint(y) & 0xFFFF0000u);
    __nv_bfloat162 p = __floats2bfloat162_rn(lx, ly);
    return *(uint32_t*)&p;
}
__device__ __forceinline__ void store_hl(__nv_bfloat16* H, __nv_bfloat16* L, long i, float v){
    uint32_t u = __float_as_uint(v);
    ((unsigned short*)H)[i] = (unsigned short)(u >> 16);
    float r = v - __uint_as_float(u & 0xFFFF0000u);
    L[i] = __float2bfloat16(r);
}

// ---------------- bf16 hi/lo NT GEMM, cp.async pipelined, 2 CTA/SM --------
// D[m,n] = sum_p sum_k A_p[m,k]*B_p[n,k], 3 bf16 passes (hh + hl + lh)
// EPI: 0 fp32 out; 3 split-bf16 out; 4 fp32 out scaled by gs[b*CCH+m];
//      5 (psi_v): BN+ReLU + deinterleave-split E/O out + row sumsq partials
//      6 (psi_l): BN+ReLU(col) + split out + row sumsq partials
struct GArgs {
    const __nv_bfloat16 *A0h, *A0l, *B0h, *B0l;
    const __nv_bfloat16 *A1h, *A1l, *B1h, *B1l;
    void *C, *C2, *C3, *C4;
    float *P;
    const float *gs, *bs;
    long sA, sB, sC;
    int lda, ldb, ldc, K;
};

#define STG3   32768
#define G_SMEM (3 * STG3)

template<int EPI, int NP>
__global__ void __launch_bounds__(256, 2) mma_gemm(GArgs a)
{
    extern __shared__ __align__(128) char smem[];
    const int tid = threadIdx.x, w = tid >> 5, lane = tid & 31;
    const int bn0 = blockIdx.x << 7, bm0 = blockIdx.y << 7, b = blockIdx.z;
    const int KS = a.K >> 5;
    const int NS = KS * NP;
    const uint32_t sbase = cvta_s(smem);
    const int wm = w >> 2, wn = w & 3;

    const int r0 = tid >> 2, ch = tid & 3;
    const uint32_t q16 = (uint32_t)((ch ^ ((r0 >> 1) & 3)) * 16);

    auto issue = [&](int s){
        if (s >= NS) return;
        int p = (NP == 2 && s >= KS) ? 1 : 0;
        long k0 = (long)(s - p * KS) * 32;
        const __nv_bfloat16* srcs[4] = {
            (p ? a.A1h : a.A0h) + (long)b * a.sA + (long)bm0 * a.lda + k0,
            (p ? a.A1l : a.A0l) + (long)b * a.sA + (long)bm0 * a.lda + k0,
            (p ? a.B1h : a.B0h) + (long)b * a.sB + (long)bn0 * a.ldb + k0,
            (p ? a.B1l : a.B0l) + (long)b * a.sB + (long)bn0 * a.ldb + k0
        };
        uint32_t dst0 = sbase + (uint32_t)(s % 3) * STG3 + (uint32_t)r0 * 64u + q16;
        #pragma unroll
        for (int sub = 0; sub < 4; sub++){
            long ld = (sub < 2) ? a.lda : a.ldb;
            const __nv_bfloat16* sp = srcs[sub] + (long)r0 * ld + ch * 8;
            cpa16(dst0 + sub * 8192,        sp);
            cpa16(dst0 + sub * 8192 + 4096, sp + 64 * ld);
        }
    };

    float acc[4][4][4];
    #pragma unroll
    for (int i = 0; i < 4; i++)
        #pragma unroll
        for (int j = 0; j < 4; j++)
            #pragma unroll
            for (int t = 0; t < 4; t++) acc[i][j][t] = 0.0f;

    const int aRow = wm * 64 + (lane & 15);
    const uint32_t lqA = (uint32_t)(((lane & 15) >> 1) & 3);
    const uint32_t aC0 = (uint32_t)(lane >> 4);
    const int bRow = wn * 32 + (lane & 7) + ((lane >> 4) & 1) * 8;
    const uint32_t lqB = (uint32_t)(((lane & 7) >> 1) & 3);
    const uint32_t bC0 = (uint32_t)((lane >> 3) & 1);

    issue(0); CP_COMMIT();
    issue(1); CP_COMMIT();

    for (int i = 0; i < NS; i++){
        CP_WAIT1();
        __syncthreads();
        issue(i + 2);
        CP_COMMIT();

        const uint32_t stb = sbase + (uint32_t)(i % 3) * STG3;
        #pragma unroll
        for (int ks = 0; ks < 2; ks++){
            const uint32_t qa = ((aC0 + 2 * ks) ^ lqA) * 16u;
            const uint32_t qb = ((bC0 + 2 * ks) ^ lqB) * 16u;
            uint32_t Afh[4][4], Bfh[2][4], Bfl[2][4];
            #pragma unroll
            for (int mi = 0; mi < 4; mi++){
                uint32_t ad = stb + (uint32_t)(aRow + mi * 16) * 64u + qa;
                LDSM4(Afh[mi], ad);
            }
            #pragma unroll
            for (int nb = 0; nb < 2; nb++){
                uint32_t bd = stb + 16384u + (uint32_t)(bRow + nb * 16) * 64u + qb;
                LDSM4(Bfh[nb], bd);
                LDSM4(Bfl[nb], bd + 8192);
            }
            #pragma unroll
            for (int mi = 0; mi < 4; mi++)
                #pragma unroll
                for (int ni = 0; ni < 4; ni++){
                    int nb = ni >> 1, h = (ni & 1) * 2;
                    MMA16816(acc[mi][ni], Afh[mi], Bfh[nb][h], Bfh[nb][h + 1]);
                }
            #pragma unroll
            for (int mi = 0; mi < 4; mi++)
                #pragma unroll
                for (int ni = 0; ni < 4; ni++){
                    int nb = ni >> 1, h = (ni & 1) * 2;
                    MMA16816(acc[mi][ni], Afh[mi], Bfl[nb][h], Bfl[nb][h + 1]);
                }
            uint32_t Afl[4][4];
            #pragma unroll
            for (int mi = 0; mi < 4; mi++){
                uint32_t ad = stb + 8192u + (uint32_t)(aRow + mi * 16) * 64u + qa;
                LDSM4(Afl[mi], ad);
            }
            #pragma unroll
            for (int mi = 0; mi < 4; mi++)
                #pragma unroll
                for (int ni = 0; ni < 4; ni++){
                    int nb = ni >> 1, h = (ni & 1) * 2;
                    MMA16816(acc[mi][ni], Afl[mi], Bfh[nb][h], Bfh[nb][h + 1]);
                }
        }
    }

    // ---- epilogue
    const int r1 = lane >> 2, cq = (lane & 3) * 2;
    if (EPI == 3){
        __nv_bfloat16* Ch = (__nv_bfloat16*)a.C;
        __nv_bfloat16* Cl = (__nv_bfloat16*)a.C2;
        const long cb = (long)b * a.sC;
        #pragma unroll
        for (int mi = 0; mi < 4; mi++){
            int m0 = bm0 + wm * 64 + mi * 16 + r1;
            #pragma unroll
            for (int ni = 0; ni < 4; ni++){
                int n = bn0 + wn * 32 + ni * 8 + cq;
                float v0 = acc[mi][ni][0], v1 = acc[mi][ni][1];
                float v2 = acc[mi][ni][2], v3 = acc[mi][ni][3];
                *(uint32_t*)(Ch + cb + (long)m0 * a.ldc + n)       = pack_hi(v0, v1);
                *(uint32_t*)(Cl + cb + (long)m0 * a.ldc + n)       = pack_lo(v0, v1);
                *(uint32_t*)(Ch + cb + (long)(m0 + 8) * a.ldc + n) = pack_hi(v2, v3);
                *(uint32_t*)(Cl + cb + (long)(m0 + 8) * a.ldc + n) = pack_lo(v2, v3);
            }
        }
    } else if (EPI == 5){
        __nv_bfloat16 *Ehp = (__nv_bfloat16*)a.C,  *Elp = (__nv_bfloat16*)a.C2;
        __nv_bfloat16 *Ohp = (__nv_bfloat16*)a.C3, *Olp = (__nv_bfloat16*)a.C4;
        #pragma unroll
        for (int mi = 0; mi < 4; mi++){
            int m0 = bm0 + wm * 64 + mi * 16 + r1;
            float s0 = a.gs[m0] * BN_RS,     b0_ = a.bs[m0];
            float s1 = a.gs[m0 + 8] * BN_RS, b1_ = a.bs[m0 + 8];
            float sq0 = 0.f, sq1 = 0.f;
            #pragma unroll
            for (int ni = 0; ni < 4; ni++){
                int n = bn0 + wn * 32 + ni * 8 + cq;  // even col
                long ci = n >> 1;
                float v0 = fmaxf(fmaf(acc[mi][ni][0], s0, b0_), 0.f);
                float v1 = fmaxf(fmaf(acc[mi][ni][1], s0, b0_), 0.f);
                float v2 = fmaxf(fmaf(acc[mi][ni][2], s1, b1_), 0.f);
                float v3 = fmaxf(fmaf(acc[mi][ni][3], s1, b1_), 0.f);
                sq0 += v0 * v0 + v1 * v1;
                sq1 += v2 * v2 + v3 * v3;
                long i0 = ((long)b * DD + m0) * HWD + ci;
                long i1 = ((long)b * DD + m0 + 8) * HWD + ci;
                store_hl(Ehp, Elp, i0, v0);
                store_hl(Ohp, Olp, i0, v1);
                store_hl(Ehp, Elp, i1, v2);
                store_hl(Ohp, Olp, i1, v3);
            }
            sq0 += __shfl_xor_sync(0xffffffffu, sq0, 1);
            sq0 += __shfl_xor_sync(0xffffffffu, sq0, 2);
            sq1 += __shfl_xor_sync(0xffffffffu, sq1, 1);
            sq1 += __shfl_xor_sync(0xffffffffu, sq1, 2);
            if ((lane & 3) == 0){
                a.P[(((long)b * DD + m0) * 16 + blockIdx.x) * 4 + wn]     = sq0;
                a.P[(((long)b * DD + m0 + 8) * 16 + blockIdx.x) * 4 + wn] = sq1;
            }
        }
    } else if (EPI == 6){
        __nv_bfloat16* Ch = (__nv_bfloat16*)a.C;
        __nv_bfloat16* Cl = (__nv_bfloat16*)a.C2;
        const long cb = (long)b * a.sC;
        #pragma unroll
        for (int mi = 0; mi < 4; mi++){
            int m0 = bm0 + wm * 64 + mi * 16 + r1;
            float sq0 = 0.f, sq1 = 0.f;
            #pragma unroll
            for (int ni = 0; ni < 4; ni++){
                int n = bn0 + wn * 32 + ni * 8 + cq;
                float gs0 = a.gs[n] * BN_RS, bb0 = a.bs[n];
                float gs1 = a.gs[n + 1] * BN_RS, bb1 = a.bs[n + 1];
                float v0 = fmaxf(fmaf(acc[mi][ni][0], gs0, bb0), 0.f);
                float v1 = fmaxf(fmaf(acc[mi][ni][1], gs1, bb1), 0.f);
                float v2 = fmaxf(fmaf(acc[mi][ni][2], gs0, bb0), 0.f);
                float v3 = fmaxf(fmaf(acc[mi][ni][3], gs1, bb1), 0.f);
                sq0 += v0 * v0 + v1 * v1;
                sq1 += v2 * v2 + v3 * v3;
                *(uint32_t*)(Ch + cb + (long)m0 * a.ldc + n)       = pack_hi(v0, v1);
                *(uint32_t*)(Cl + cb + (long)m0 * a.ldc + n)       = pack_lo(v0, v1);
                *(uint32_t*)(Ch + cb + (long)(m0 + 8) * a.ldc + n) = pack_hi(v2, v3);
                *(uint32_t*)(Cl + cb + (long)(m0 + 8) * a.ldc + n) = pack_lo(v2, v3);
            }
            sq0 += __shfl_xor_sync(0xffffffffu, sq0, 1);
            sq0 += __shfl_xor_sync(0xffffffffu, sq0, 2);
            sq1 += __shfl_xor_sync(0xffffffffu, sq1, 1);
            sq1 += __shfl_xor_sync(0xffffffffu, sq1, 2);
            if ((lane & 3) == 0){
                int pc = (bn0 >> 7) * 4 + wn;
                a.P[((long)b * CCH + m0) * 8 + pc]     = sq0;
                a.P[((long)b * CCH + m0 + 8) * 8 + pc] = sq1;
            }
        }
    } else {  // EPI 0 or 4
        float* Cb = (float*)a.C + (long)b * a.sC;
        #pragma unroll
        for (int mi = 0; mi < 4; mi++){
            int m0 = bm0 + wm * 64 + mi * 16 + r1;
            float rz0 = 1.f, rz1 = 1.f;
            if (EPI == 4){
                rz0 = a.gs[(long)b * CCH + m0];
                rz1 = a.gs[(long)b * CCH + m0 + 8];
            }
            #pragma unroll
            for (int ni = 0; ni < 4; ni++){
                int n = bn0 + wn * 32 + ni * 8 + cq;
                float v0 = acc[mi][ni][0] * rz0, v1 = acc[mi][ni][1] * rz0;
                float v2 = acc[mi][ni][2] * rz1, v3 = acc[mi][ni][3] * rz1;
                *(float2*)(Cb + (long)m0 * a.ldc + n)       = make_float2(v0, v1);
                *(float2*)(Cb + (long)(m0 + 8) * a.ldc + n) = make_float2(v2, v3);
            }
        }
    }
}

// ---------------- reductions ----------------
__device__ __forceinline__ float warpSum(float v){
    #pragma unroll
    for (int o = 16; o; o >>= 1) v += __shfl_xor_sync(0xffffffffu, v, o);
    return v;
}
__device__ __forceinline__ float warpMax(float v){
    #pragma unroll
    for (int o = 16; o; o >>= 1) v = fmaxf(v, __shfl_xor_sync(0xffffffffu, v, o));
    return v;
}
__device__ __forceinline__ float blockSum(float v){
    __shared__ float sh[32];
    int w = threadIdx.x >> 5, l = threadIdx.x & 31;
    v = warpSum(v);
    if (l == 0) sh[w] = v;
    __syncthreads();
    int nw = blockDim.x >> 5;
    if (w == 0){ float x = (l < nw) ? sh[l] : 0.0f; x = warpSum(x); if (l == 0) sh[0] = x; }
    __syncthreads();
    float r = sh[0];
    __syncthreads();
    return r;
}
__device__ __forceinline__ float blockMax(float v){
    __shared__ float sh[32];
    int w = threadIdx.x >> 5, l = threadIdx.x & 31;
    v = warpMax(v);
    if (l == 0) sh[w] = v;
    __syncthreads();
    int nw = blockDim.x >> 5;
    if (w == 0){ float x = (l < nw) ? sh[l] : -INFINITY; x = warpMax(x); if (l == 0) sh[0] = x; }
    __syncthreads();
    float r = sh[0];
    __syncthreads();
    return r;
}

// ---------------- elementwise kernels ----------------
__global__ void __launch_bounds__(256)
k_split(const float4* __restrict__ in, uint2* __restrict__ hi, uint2* __restrict__ lo, int n4)
{
    int i = blockIdx.x * blockDim.x + threadIdx.x;
    int stride = gridDim.x * blockDim.x;
    for (; i < n4; i += stride){
        float4 v = in[i];
        uint2 h, l;
        split16(v, h, l);
        hi[i] = h;
        lo[i] = l;
    }
}

// reduce partial sum-squares -> inverse norms
__global__ void __launch_bounds__(256)
k_rinv(const float* __restrict__ P, float* __restrict__ R, int cnt, int rows)
{
    int row = blockIdx.x * blockDim.x + threadIdx.x;
    if (row >= rows) return;
    const float* p = P + (long)row * cnt;
    float s = 0.0f;
    for (int i = 0; i < cnt; i++) s += p[i];
    R[row] = 1.0f / fmaxf(sqrtf(s), 1e-12f);
}

// transpose lat_hi/lo [b,256,1024] -> latT_hi/lo [b,1024,256]
__global__ void __launch_bounds__(256)
k_transpose(const uint32_t* __restrict__ sH, const uint32_t* __restrict__ sL,
            uint32_t* __restrict__ dH, uint32_t* __restrict__ dL)
{
    __shared__ unsigned short tile[32][34];
    const int b = blockIdx.z, h0 = blockIdx.x * 32, d0 = blockIdx.y * 32;
    const int t = threadIdx.x;
    const uint32_t* srcs[2] = {sH, sL};
    uint32_t* dsts[2] = {dH, dL};
    #pragma unroll
    for (int m = 0; m < 2; m++){
        #pragma unroll
        for (int i = 0; i < 2; i++){
            int s = t + i * 256;
            int d = s >> 4, hu = s & 15;
            uint32_t v = srcs[m][(long)(b * 256 + d0 + d) * 512 + (h0 >> 1) + hu];
            tile[d][2 * hu]     = (unsigned short)(v & 0xFFFFu);
            tile[d][2 * hu + 1] = (unsigned short)(v >> 16);
        }
        __syncthreads();
        #pragma unroll
        for (int i = 0; i < 2; i++){
            int s = t + i * 256;
            int h = s >> 4, du = s & 15;
            uint32_t v = (uint32_t)tile[2 * du][h] | ((uint32_t)tile[2 * du + 1][h] << 16);
            dsts[m][(long)(b * 1024 + h0 + h) * 128 + (d0 >> 1) + du] = v;
        }
        __syncthreads();
    }
}

// latent row inverse norms from hi/lo (raw lat)
__global__ void __launch_bounds__(256)
k_latnorm(const uint32_t* __restrict__ H, const uint32_t* __restrict__ L, float* __restrict__ R)
{
    long row = blockIdx.x;
    long base = row * 512;
    int t = threadIdx.x;
    float s = 0.0f;
    #pragma unroll
    for (int i = 0; i < 2; i++){
        long idx = base + t + i * 256;
        uint32_t uh = H[idx], ul = L[idx];
        float2 fh = __bfloat1622float2(*(__nv_bfloat162*)&uh);
        float2 fl = __bfloat1622float2(*(__nv_bfloat162*)&ul);
        float v0 = fh.x + fl.x, v1 = fh.y + fl.y;
        s += v0 * v0 + v1 * v1;
    }
    s = blockSum(s);
    if (t == 0) R[row] = 1.0f / fmaxf(sqrtf(s), 1e-12f);
}

// softmax over scaled gram rows; fold invv column scale; write split bf16
__global__ void __launch_bounds__(256)
k_softmax(const float* __restrict__ G, const float* __restrict__ R,
          const float* __restrict__ IV,
          uint32_t* __restrict__ Gh, uint32_t* __restrict__ Gl)
{
    long row = blockIdx.x;
    long bb = row >> 8;
    int t = threadIdx.x;
    float ri = R[row];
    float re = R[(bb << 8) + t];
    float x = G[row * 256 + t] * ri * re;
    float mx = blockMax(x);
    float p = expf(x - mx);
    float sm = blockSum(p);
    float g = (p / sm) * IV[(bb << 8) + t];   // fold psi_v inverse norm (column e)
    float gn = __shfl_down_sync(0xffffffffu, g, 1);
    if ((t & 1) == 0){
        Gh[row * 128 + (t >> 1)] = pack_hi(g, gn);
        Gl[row * 128 + (t >> 1)] = pack_lo(g, gn);
    }
}

// ---------------- launch ----------------
extern "C" void kernel_launch(void* const* d_in, const int* in_sizes, int n_in,
                              void* d_out, int out_size)
{
    const float* v2l = (const float*)d_in[0];
    const float* l2v = (const float*)d_in[1];
    const float* wv  = (const float*)d_in[2];
    const float* gv  = (const float*)d_in[3];
    const float* bv  = (const float*)d_in[4];
    const float* wl  = (const float*)d_in[5];
    const float* gl  = (const float*)d_in[6];
    const float* bl  = (const float*)d_in[7];
    float* out = (float*)d_out;

    float *G, *invr, *P1, *P2, *invv, *invz;
    __nv_bfloat16 *v2lh, *v2ll, *l2vh, *l2vl, *wvh, *wvl, *wlh, *wll;
    __nv_bfloat16 *Eh, *El, *Oh, *Ol, *Zh, *Zlo, *lath, *latl, *latTh, *latTl;
    __nv_bfloat16 *Ghb, *Glb, *l2Th, *l2Tl;
    cudaGetSymbolAddress((void**)&G, d_G);
    cudaGetSymbolAddress((void**)&invr, d_invr);
    cudaGetSymbolAddress((void**)&P1, d_P1);
    cudaGetSymbolAddress((void**)&P2, d_P2);
    cudaGetSymbolAddress((void**)&invv, d_invv);
    cudaGetSymbolAddress((void**)&invz, d_invz);
    cudaGetSymbolAddress((void**)&v2lh, g_v2lh); cudaGetSymbolAddress((void**)&v2ll, g_v2ll);
    cudaGetSymbolAddress((void**)&l2vh, g_l2vh); cudaGetSymbolAddress((void**)&l2vl, g_l2vl);
    cudaGetSymbolAddress((void**)&wvh, g_wvh);   cudaGetSymbolAddress((void**)&wvl, g_wvl);
    cudaGetSymbolAddress((void**)&wlh, g_wlh);   cudaGetSymbolAddress((void**)&wll, g_wll);
    cudaGetSymbolAddress((void**)&Eh, g_Eh);     cudaGetSymbolAddress((void**)&El, g_El);
    cudaGetSymbolAddress((void**)&Oh, g_Oh);     cudaGetSymbolAddress((void**)&Ol, g_Ol);
    cudaGetSymbolAddress((void**)&Zh, g_Zh);     cudaGetSymbolAddress((void**)&Zlo, g_Zlo);
    cudaGetSymbolAddress((void**)&lath, g_lath); cudaGetSymbolAddress((void**)&latl, g_latl);
    cudaGetSymbolAddress((void**)&latTh, g_latTh); cudaGetSymbolAddress((void**)&latTl, g_latTl);
    cudaGetSymbolAddress((void**)&Ghb, g_Gh);    cudaGetSymbolAddress((void**)&Glb, g_Gl);
    cudaGetSymbolAddress((void**)&l2Th, g_l2Th); cudaGetSymbolAddress((void**)&l2Tl, g_l2Tl);

    cudaFuncSetAttribute(mma_gemm<0,1>, cudaFuncAttributeMaxDynamicSharedMemorySize, G_SMEM);
    cudaFuncSetAttribute(mma_gemm<3,1>, cudaFuncAttributeMaxDynamicSharedMemorySize, G_SMEM);
    cudaFuncSetAttribute(mma_gemm<3,2>, cudaFuncAttributeMaxDynamicSharedMemorySize, G_SMEM);
    cudaFuncSetAttribute(mma_gemm<4,1>, cudaFuncAttributeMaxDynamicSharedMemorySize, G_SMEM);
    cudaFuncSetAttribute(mma_gemm<5,1>, cudaFuncAttributeMaxDynamicSharedMemorySize, G_SMEM);
    cudaFuncSetAttribute(mma_gemm<6,1>, cudaFuncAttributeMaxDynamicSharedMemorySize, G_SMEM);

    const long FEAT = (long)CCH * HWD;
    dim3 blk(256);

    // 0) splits of raw inputs + weights
    k_split<<<8192, blk>>>((const float4*)v2l, (uint2*)v2lh, (uint2*)v2ll, (int)(BATCH*FEAT/4));
    k_split<<<8192, blk>>>((const float4*)l2v, (uint2*)l2vh, (uint2*)l2vl, (int)(BATCH*FEAT/4));
    k_split<<<256, blk>>>((const float4*)wv, (uint2*)wvh, (uint2*)wvl, DD*HWD/4);
    k_split<<<256, blk>>>((const float4*)wl, (uint2*)wlh, (uint2*)wll, DD*HWD/4);

    // 1) psi_v: raw BN+ReLU, deinterleave-split to E/O + sumsq partials
    {
        GArgs a = { wvh, wvl, v2lh, v2ll, nullptr, nullptr, nullptr, nullptr,
                    Eh, El, Oh, Ol, P1, gv, bv,
                    0, FEAT, 0, HWD, HWD, 0, HWD };
        mma_gemm<5,1><<<dim3(CCH/128, DD/128, BATCH), blk, G_SMEM>>>(a);
    }
    // 1b) invv = 1/||psi_v row||
    k_rinv<<<(BATCH*DD + 255)/256, blk>>>(P1, invv, 64, BATCH*DD);

    // 2) psi_l: raw BN+ReLU, split Zh/Zlo + sumsq partials
    {
        GArgs a = { l2vh, l2vl, wlh, wll, nullptr, nullptr, nullptr, nullptr,
                    Zh, Zlo, nullptr, nullptr, P2, gl, bl,
                    FEAT, 0, (long)CCH*DD, HWD, HWD, DD, HWD };
        mma_gemm<6,1><<<dim3(DD/128, CCH/128, BATCH), blk, G_SMEM>>>(a);
    }
    // 2b) invz = 1/||psi_l row||
    k_rinv<<<(BATCH*CCH + 255)/256, blk>>>(P2, invz, 8, BATCH*CCH);

    // 5) rawlat = Yv_even.Vlow^T + Yv_odd.Vhigh^T  -> split bf16
    {
        GArgs a = { Eh, El, v2lh, v2ll, Oh, Ol, v2lh + (long)HWD*HWD, v2ll + (long)HWD*HWD,
                    lath, latl, nullptr, nullptr, nullptr, nullptr, nullptr,
                    (long)DD*HWD, FEAT, (long)DD*HWD, HWD, HWD, HWD, HWD };
        mma_gemm<3,2><<<dim3(HWD/128, DD/128, BATCH), blk, G_SMEM>>>(a);
    }
    // 6) transpose rawlat -> latT
    k_transpose<<<dim3(32, 8, BATCH), blk>>>(
        (const uint32_t*)lath, (const uint32_t*)latl, (uint32_t*)latTh, (uint32_t*)latTl);
    // 7) rawlat row inverse norms
    k_latnorm<<<BATCH*DD, blk>>>((const uint32_t*)lath, (const uint32_t*)latl, invr);
    // 8) G = rawlat . rawlat^T (fp32)
    {
        GArgs a = { lath, latl, lath, latl, nullptr, nullptr, nullptr, nullptr,
                    G, nullptr, nullptr, nullptr, nullptr, nullptr, nullptr,
                    (long)DD*HWD, (long)DD*HWD, (long)DD*DD, HWD, HWD, DD, HWD };
        mma_gemm<0,1><<<dim3(DD/128, DD/128, BATCH), blk, G_SMEM>>>(a);
    }
    // 9) aff' = softmax(G·ri·re) * invv[e]  -> split bf16
    k_softmax<<<BATCH*DD, blk>>>(G, invr, invv, (uint32_t*)Ghb, (uint32_t*)Glb);
    // 10) l2T = latT . aff'^T  -> split bf16
    {
        GArgs a = { latTh, latTl, Ghb, Glb, nullptr, nullptr, nullptr, nullptr,
                    l2Th, l2Tl, nullptr, nullptr, nullptr, nullptr, nullptr,
                    (long)HWD*DD, (long)DD*DD, (long)HWD*DD, DD, DD, DD, DD };
        mma_gemm<3,1><<<dim3(DD/128, HWD/128, BATCH), blk, G_SMEM>>>(a);
    }
    // 11) out = (Z . l2T^T) * invz[c]  (fp32 out)
    {
        GArgs a = { Zh, Zlo, l2Th, l2Tl, nullptr, nullptr, nullptr, nullptr,
                    out, nullptr, nullptr, nullptr, nullptr, invz, nullptr,
                    (long)CCH*DD, (long)HWD*DD, (long)CCH*HWD, DD, DD, HWD, DD };
        mma_gemm<4,1><<<dim3(HWD/128, CCH/128, BATCH), blk, G_SMEM>>>(a);
    }
}

// round 12
// speedup vs baseline: 1.3365x; 1.3330x over previous
#include <cuda_runtime.h>
#include <cuda_fp16.h>
#include <math.h>
#include <stdint.h>

#define BATCH 16
#define CCH   2048
#define HWD   1024
#define DD    256
#define BN_RS 0.9999950000374997f   // 1/sqrt(1 + 1e-5)

// ---------------- scratch (device globals; no allocation) ----------------
__device__ __align__(16) float d_Yv [BATCH * DD  * CCH];
__device__ __align__(16) float d_Zl [BATCH * CCH * DD ];
__device__ __align__(16) float d_G  [BATCH * DD  * DD ];
__device__ float d_invr[BATCH * DD];

// fp16 hi/lo split operand storage (lo only where used as A-side)
__device__ __align__(16) __half g_v2lh[BATCH*CCH*HWD];                      // B-side: hi only
__device__ __align__(16) __half g_l2vh[BATCH*CCH*HWD], g_l2vl[BATCH*CCH*HWD];
__device__ __align__(16) __half g_wvh[DD*HWD], g_wvl[DD*HWD];
__device__ __align__(16) __half g_wlh[DD*HWD];                              // B-side: hi only
__device__ __align__(16) __half g_Eh[BATCH*DD*HWD], g_El[BATCH*DD*HWD];
__device__ __align__(16) __half g_Oh[BATCH*DD*HWD], g_Ol[BATCH*DD*HWD];
__device__ __align__(16) __half g_Zh[BATCH*CCH*DD], g_Zlo[BATCH*CCH*DD];
__device__ __align__(16) __half g_lath[BATCH*DD*HWD], g_latl[BATCH*DD*HWD];
__device__ __align__(16) __half g_latTh[BATCH*HWD*DD], g_latTl[BATCH*HWD*DD];
__device__ __align__(16) __half g_Gh[BATCH*DD*DD];                          // B-side: hi only
__device__ __align__(16) __half g_l2Th[BATCH*HWD*DD];                       // B-side: hi only

// ---------------- helpers ----------------
__device__ __forceinline__ uint32_t cvta_s(const void* p){
    return (uint32_t)__cvta_generic_to_shared(p);
}
__device__ __forceinline__ void cpa16(uint32_t d, const void* s){
    asm volatile("cp.async.cg.shared.global [%0], [%1], 16;" :: "r"(d), "l"(s));
}
#define CP_COMMIT() asm volatile("cp.async.commit_group;")
#define CP_WAIT2()  asm volatile("cp.async.wait_group 2;")

#define LDSM4(R, addr) \
    asm volatile("ldmatrix.sync.aligned.m8n8.x4.shared.b16 {%0,%1,%2,%3}, [%4];" \
        : "=r"((R)[0]), "=r"((R)[1]), "=r"((R)[2]), "=r"((R)[3]) : "r"(addr))

#define MMA16816(d, A, b0, b1) \
    asm volatile("mma.sync.aligned.m16n8k16.row.col.f32.f16.f16.f32 " \
        "{%0,%1,%2,%3}, {%4,%5,%6,%7}, {%8,%9}, {%0,%1,%2,%3};" \
        : "+f"((d)[0]), "+f"((d)[1]), "+f"((d)[2]), "+f"((d)[3]) \
        : "r"((A)[0]), "r"((A)[1]), "r"((A)[2]), "r"((A)[3]), "r"(b0), "r"(b1))

__device__ __forceinline__ uint32_t packh(float x, float y){
    __half2 h = __floats2half2_rn(x, y);
    return *(uint32_t*)&h;
}
__device__ __forceinline__ uint32_t packl(float x, float y){
    float lx = x - __half2float(__float2half_rn(x));
    float ly = y - __half2float(__float2half_rn(y));
    return packh(lx, ly);
}
__device__ __forceinline__ void split16h(float4 v, uint2& hi, uint2& lo){
    hi.x = packh(v.x, v.y); hi.y = packh(v.z, v.w);
    lo.x = packl(v.x, v.y); lo.y = packl(v.z, v.w);
}

// ---------------- fp16 hi/lo NT GEMM, cp.async 4-stage, 2 CTA/SM ----------
// D[m,n] = sum_p sum_k A_p[m,k]*B_p[n,k], 2 passes: Ah*Bh + Al*Bh
// EPI: 0 fp32; 1 BN+ReLU row (fp32); 2 BN+ReLU col (fp32);
//      3 split fp16 out (hi C, lo C2); 7 fp16 hi-only out (C)
struct GArgs {
    const __half *A0h, *A0l, *B0h;
    const __half *A1h, *A1l, *B1h;
    void *C, *C2;
    const float *gs, *bs;
    long sA, sB, sC;
    int lda, ldb, ldc, K;
};

// stage = 24KB: Ah@0, Al@8K, Bh@16K. Rows 64B, quarter q = ch ^ ((row>>1)&3).
#define STG4   24576
#define G_SMEM (4 * STG4)

template<int EPI, int NP>
__global__ void __launch_bounds__(256, 2) mma_gemm(GArgs a)
{
    extern __shared__ __align__(128) char smem[];
    const int tid = threadIdx.x, w = tid >> 5, lane = tid & 31;
    const int bn0 = blockIdx.x << 7, bm0 = blockIdx.y << 7, b = blockIdx.z;
    const int KS = a.K >> 5;
    const int NS = KS * NP;
    const uint32_t sbase = cvta_s(smem);
    const int wm = w >> 2, wn = w & 3;

    const int r0 = tid >> 2, ch = tid & 3;
    const uint32_t q16 = (uint32_t)((ch ^ ((r0 >> 1) & 3)) * 16);

    auto issue = [&](int s){
        if (s >= NS) return;
        int p = (NP == 2 && s >= KS) ? 1 : 0;
        long k0 = (long)(s - p * KS) * 32;
        const __half* srcs[3] = {
            (p ? a.A1h : a.A0h) + (long)b * a.sA + (long)bm0 * a.lda + k0,
            (p ? a.A1l : a.A0l) + (long)b * a.sA + (long)bm0 * a.lda + k0,
            (p ? a.B1h : a.B0h) + (long)b * a.sB + (long)bn0 * a.ldb + k0
        };
        uint32_t dst0 = sbase + (uint32_t)(s & 3) * STG4 + (uint32_t)r0 * 64u + q16;
        #pragma unroll
        for (int sub = 0; sub < 3; sub++){
            long ld = (sub < 2) ? a.lda : a.ldb;
            const __half* sp = srcs[sub] + (long)r0 * ld + ch * 8;
            cpa16(dst0 + sub * 8192,        sp);
            cpa16(dst0 + sub * 8192 + 4096, sp + 64 * ld);
        }
    };

    float acc[4][4][4];
    #pragma unroll
    for (int i = 0; i < 4; i++)
        #pragma unroll
        for (int j = 0; j < 4; j++)
            #pragma unroll
            for (int t = 0; t < 4; t++) acc[i][j][t] = 0.0f;

    const int aRow = wm * 64 + (lane & 15);
    const uint32_t lqA = (uint32_t)(((lane & 15) >> 1) & 3);
    const uint32_t aC0 = (uint32_t)(lane >> 4);
    const int bRow = wn * 32 + (lane & 7) + ((lane >> 4) & 1) * 8;
    const uint32_t lqB = (uint32_t)(((lane & 7) >> 1) & 3);
    const uint32_t bC0 = (uint32_t)((lane >> 3) & 1);

    issue(0); CP_COMMIT();
    issue(1); CP_COMMIT();
    issue(2); CP_COMMIT();

    for (int i = 0; i < NS; i++){
        CP_WAIT2();
        __syncthreads();
        issue(i + 3);        // buffer (i+3)&3 == (i-1)&3; compute of i-1 done by barrier
        CP_COMMIT();

        const uint32_t stb = sbase + (uint32_t)(i & 3) * STG4;
        #pragma unroll
        for (int ks = 0; ks < 2; ks++){
            const uint32_t qa = ((aC0 + 2 * ks) ^ lqA) * 16u;
            const uint32_t qb = ((bC0 + 2 * ks) ^ lqB) * 16u;
            uint32_t Afh[4][4], Bfh[2][4];
            #pragma unroll
            for (int mi = 0; mi < 4; mi++){
                uint32_t ad = stb + (uint32_t)(aRow + mi * 16) * 64u + qa;
                LDSM4(Afh[mi], ad);
            }
            #pragma unroll
            for (int nb = 0; nb < 2; nb++){
                uint32_t bd = stb + 16384u + (uint32_t)(bRow + nb * 16) * 64u + qb;
                LDSM4(Bfh[nb], bd);
            }
            // pass 1: Ah*Bh
            #pragma unroll
            for (int mi = 0; mi < 4; mi++)
                #pragma unroll
                for (int ni = 0; ni < 4; ni++){
                    int nb = ni >> 1, h = (ni & 1) * 2;
                    MMA16816(acc[mi][ni], Afh[mi], Bfh[nb][h], Bfh[nb][h + 1]);
                }
            // deferred Al loads (register pressure)
            uint32_t Afl[4][4];
            #pragma unroll
            for (int mi = 0; mi < 4; mi++){
                uint32_t ad = stb + 8192u + (uint32_t)(aRow + mi * 16) * 64u + qa;
                LDSM4(Afl[mi], ad);
            }
            // pass 2: Al*Bh
            #pragma unroll
            for (int mi = 0; mi < 4; mi++)
                #pragma unroll
                for (int ni = 0; ni < 4; ni++){
                    int nb = ni >> 1, h = (ni & 1) * 2;
                    MMA16816(acc[mi][ni], Afl[mi], Bfh[nb][h], Bfh[nb][h + 1]);
                }
        }
    }

    // ---- epilogue
    const int r1 = lane >> 2, cq = (lane & 3) * 2;
    if (EPI == 3 || EPI == 7){
        __half* Ch = (__half*)a.C;
        __half* Cl = (__half*)a.C2;
        const long cb = (long)b * a.sC;
        #pragma unroll
        for (int mi = 0; mi < 4; mi++){
            int m0 = bm0 + wm * 64 + mi * 16 + r1;
            #pragma unroll
            for (int ni = 0; ni < 4; ni++){
                int n = bn0 + wn * 32 + ni * 8 + cq;
                float v0 = acc[mi][ni][0], v1 = acc[mi][ni][1];
                float v2 = acc[mi][ni][2], v3 = acc[mi][ni][3];
                *(uint32_t*)(Ch + cb + (long)m0 * a.ldc + n)       = packh(v0, v1);
                *(uint32_t*)(Ch + cb + (long)(m0 + 8) * a.ldc + n) = packh(v2, v3);
                if (EPI == 3){
                    *(uint32_t*)(Cl + cb + (long)m0 * a.ldc + n)       = packl(v0, v1);
                    *(uint32_t*)(Cl + cb + (long)(m0 + 8) * a.ldc + n) = packl(v2, v3);
                }
            }
        }
    } else {
        float* Cb = (float*)a.C + (long)b * a.sC;
        #pragma unroll
        for (int mi = 0; mi < 4; mi++){
            int m0 = bm0 + wm * 64 + mi * 16 + r1;
            float s0 = 0.f, b0_ = 0.f, s1 = 0.f, b1_ = 0.f;
            if (EPI == 1){
                s0 = a.gs[m0] * BN_RS;     b0_ = a.bs[m0];
                s1 = a.gs[m0 + 8] * BN_RS; b1_ = a.bs[m0 + 8];
            }
            #pragma unroll
            for (int ni = 0; ni < 4; ni++){
                int n = bn0 + wn * 32 + ni * 8 + cq;
                float v0 = acc[mi][ni][0], v1 = acc[mi][ni][1];
                float v2 = acc[mi][ni][2], v3 = acc[mi][ni][3];
                if (EPI == 1){
                    v0 = fmaxf(fmaf(v0, s0, b0_), 0.f); v1 = fmaxf(fmaf(v1, s0, b0_), 0.f);
                    v2 = fmaxf(fmaf(v2, s1, b1_), 0.f); v3 = fmaxf(fmaf(v3, s1, b1_), 0.f);
                } else if (EPI == 2){
                    float gs0 = a.gs[n] * BN_RS, bb0 = a.bs[n];
                    float gs1 = a.gs[n + 1] * BN_RS, bb1 = a.bs[n + 1];
                    v0 = fmaxf(fmaf(v0, gs0, bb0), 0.f); v1 = fmaxf(fmaf(v1, gs1, bb1), 0.f);
                    v2 = fmaxf(fmaf(v2, gs0, bb0), 0.f); v3 = fmaxf(fmaf(v3, gs1, bb1), 0.f);
                }
                *(float2*)(Cb + (long)m0 * a.ldc + n)       = make_float2(v0, v1);
                *(float2*)(Cb + (long)(m0 + 8) * a.ldc + n) = make_float2(v2, v3);
            }
        }
    }
}

// ---------------- reductions ----------------
__device__ __forceinline__ float warpSum(float v){
    #pragma unroll
    for (int o = 16; o; o >>= 1) v += __shfl_xor_sync(0xffffffffu, v, o);
    return v;
}
__device__ __forceinline__ float warpMax(float v){
    #pragma unroll
    for (int o = 16; o; o >>= 1) v = fmaxf(v, __shfl_xor_sync(0xffffffffu, v, o));
    return v;
}
__device__ __forceinline__ float blockSum(float v){
    __shared__ float sh[32];
    int w = threadIdx.x >> 5, l = threadIdx.x & 31;
    v = warpSum(v);
    if (l == 0) sh[w] = v;
    __syncthreads();
    int nw = blockDim.x >> 5;
    if (w == 0){ float x = (l < nw) ? sh[l] : 0.0f; x = warpSum(x); if (l == 0) sh[0] = x; }
    __syncthreads();
    float r = sh[0];
    __syncthreads();
    return r;
}
__device__ __forceinline__ float blockMax(float v){
    __shared__ float sh[32];
    int w = threadIdx.x >> 5, l = threadIdx.x & 31;
    v = warpMax(v);
    if (l == 0) sh[w] = v;
    __syncthreads();
    int nw = blockDim.x >> 5;
    if (w == 0){ float x = (l < nw) ? sh[l] : -INFINITY; x = warpMax(x); if (l == 0) sh[0] = x; }
    __syncthreads();
    float r = sh[0];
    __syncthreads();
    return r;
}

// ---------------- elementwise kernels ----------------
// split fp32 -> fp16 hi (+ optional lo residual)
__global__ void __launch_bounds__(256)
k_split(const float4* __restrict__ in, uint2* __restrict__ hi, uint2* __restrict__ lo, int n4)
{
    int i = blockIdx.x * blockDim.x + threadIdx.x;
    int stride = gridDim.x * blockDim.x;
    for (; i < n4; i += stride){
        float4 v = in[i];
        uint2 h, l;
        split16h(v, h, l);
        hi[i] = h;
        if (lo) lo[i] = l;
    }
}

// normalize Yv rows over C=2048, deinterleave even/odd channels, write split fp16
__global__ void __launch_bounds__(256)
k_norm_v2l(const float4* __restrict__ Y,
           uint32_t* __restrict__ Eh, uint32_t* __restrict__ El,
           uint32_t* __restrict__ Oh, uint32_t* __restrict__ Ol)
{
    long row = blockIdx.x;
    const float4* y = Y + row * 512;
    int t = threadIdx.x;
    float4 v0 = y[t], v1 = y[t + 256];
    float s = v0.x*v0.x + v0.y*v0.y + v0.z*v0.z + v0.w*v0.w
            + v1.x*v1.x + v1.y*v1.y + v1.z*v1.z + v1.w*v1.w;
    s = blockSum(s);
    float inv = 1.0f / fmaxf(sqrtf(s), 1e-12f);
    long eb = row * 512;
    Eh[eb + t] = packh(v0.x * inv, v0.z * inv);
    El[eb + t] = packl(v0.x * inv, v0.z * inv);
    Oh[eb + t] = packh(v0.y * inv, v0.w * inv);
    Ol[eb + t] = packl(v0.y * inv, v0.w * inv);
    Eh[eb + t + 256] = packh(v1.x * inv, v1.z * inv);
    El[eb + t + 256] = packl(v1.x * inv, v1.z * inv);
    Oh[eb + t + 256] = packh(v1.y * inv, v1.w * inv);
    Ol[eb + t + 256] = packl(v1.y * inv, v1.w * inv);
}

// normalize Zl rows over D=256, write split fp16
__global__ void __launch_bounds__(128)
k_norm_rows(const float* __restrict__ Z, uint32_t* __restrict__ Zh, uint32_t* __restrict__ Zl)
{
    long row = blockIdx.x;
    const float2* z = (const float2*)(Z + row * 256);
    int t = threadIdx.x;
    float2 v = z[t];
    float s = blockSum(v.x * v.x + v.y * v.y);
    float inv = 1.0f / fmaxf(sqrtf(s), 1e-12f);
    Zh[row * 128 + t] = packh(v.x * inv, v.y * inv);
    Zl[row * 128 + t] = packl(v.x * inv, v.y * inv);
}

// transpose lat hi/lo [b,256,1024] -> latT hi/lo [b,1024,256] (16-bit pairs)
__global__ void __launch_bounds__(256)
k_transpose(const uint32_t* __restrict__ sH, const uint32_t* __restrict__ sL,
            uint32_t* __restrict__ dH, uint32_t* __restrict__ dL)
{
    __shared__ unsigned short tile[32][34];
    const int b = blockIdx.z, h0 = blockIdx.x * 32, d0 = blockIdx.y * 32;
    const int t = threadIdx.x;
    const uint32_t* srcs[2] = {sH, sL};
    uint32_t* dsts[2] = {dH, dL};
    #pragma unroll
    for (int m = 0; m < 2; m++){
        #pragma unroll
        for (int i = 0; i < 2; i++){
            int s = t + i * 256;
            int d = s >> 4, hu = s & 15;
            uint32_t v = srcs[m][(long)(b * 256 + d0 + d) * 512 + (h0 >> 1) + hu];
            tile[d][2 * hu]     = (unsigned short)(v & 0xFFFFu);
            tile[d][2 * hu + 1] = (unsigned short)(v >> 16);
        }
        __syncthreads();
        #pragma unroll
        for (int i = 0; i < 2; i++){
            int s = t + i * 256;
            int h = s >> 4, du = s & 15;
            uint32_t v = (uint32_t)tile[2 * du][h] | ((uint32_t)tile[2 * du + 1][h] << 16);
            dsts[m][(long)(b * 1024 + h0 + h) * 128 + (d0 >> 1) + du] = v;
        }
        __syncthreads();
    }
}

// latent row inverse norms from fp16 hi/lo
__global__ void __launch_bounds__(256)
k_latnorm(const uint32_t* __restrict__ H, const uint32_t* __restrict__ L, float* __restrict__ R)
{
    long row = blockIdx.x;
    long base = row * 512;
    int t = threadIdx.x;
    float s = 0.0f;
    #pragma unroll
    for (int i = 0; i < 2; i++){
        long idx = base + t + i * 256;
        uint32_t uh = H[idx], ul = L[idx];
        float2 fh = __half22float2(*(__half2*)&uh);
        float2 fl = __half22float2(*(__half2*)&ul);
        float v0 = fh.x + fl.x, v1 = fh.y + fl.y;
        s += v0 * v0 + v1 * v1;
    }
    s = blockSum(s);
    if (t == 0) R[row] = 1.0f / fmaxf(sqrtf(s), 1e-12f);
}

// softmax over scaled gram rows; write fp16 hi only
__global__ void __launch_bounds__(256)
k_softmax(const float* __restrict__ G, const float* __restrict__ R,
          uint32_t* __restrict__ Gh)
{
    long row = blockIdx.x;
    long bb = row >> 8;
    int t = threadIdx.x;
    float ri = R[row];
    float re = R[(bb << 8) + t];
    float x = G[row * 256 + t] * ri * re;
    float mx = blockMax(x);
    float p = expf(x - mx);
    float sm = blockSum(p);
    float g = p / sm;
    float gn = __shfl_down_sync(0xffffffffu, g, 1);
    if ((t & 1) == 0){
        Gh[row * 128 + (t >> 1)] = packh(g, gn);
    }
}

// ---------------- launch ----------------
extern "C" void kernel_launch(void* const* d_in, const int* in_sizes, int n_in,
                              void* d_out, int out_size)
{
    const float* v2l = (const float*)d_in[0];
    const float* l2v = (const float*)d_in[1];
    const float* wv  = (const float*)d_in[2];
    const float* gv  = (const float*)d_in[3];
    const float* bv  = (const float*)d_in[4];
    const float* wl  = (const float*)d_in[5];
    const float* gl  = (const float*)d_in[6];
    const float* bl  = (const float*)d_in[7];
    float* out = (float*)d_out;

    float *Yv, *Zl, *G, *invr;
    __half *v2lh, *l2vh, *l2vl, *wvh, *wvl, *wlh;
    __half *Eh, *El, *Oh, *Ol, *Zh, *Zlo, *lath, *latl, *latTh, *latTl;
    __half *Ghb, *l2Th;
    cudaGetSymbolAddress((void**)&Yv, d_Yv);
    cudaGetSymbolAddress((void**)&Zl, d_Zl);
    cudaGetSymbolAddress((void**)&G, d_G);
    cudaGetSymbolAddress((void**)&invr, d_invr);
    cudaGetSymbolAddress((void**)&v2lh, g_v2lh);
    cudaGetSymbolAddress((void**)&l2vh, g_l2vh); cudaGetSymbolAddress((void**)&l2vl, g_l2vl);
    cudaGetSymbolAddress((void**)&wvh, g_wvh);   cudaGetSymbolAddress((void**)&wvl, g_wvl);
    cudaGetSymbolAddress((void**)&wlh, g_wlh);
    cudaGetSymbolAddress((void**)&Eh, g_Eh);     cudaGetSymbolAddress((void**)&El, g_El);
    cudaGetSymbolAddress((void**)&Oh, g_Oh);     cudaGetSymbolAddress((void**)&Ol, g_Ol);
    cudaGetSymbolAddress((void**)&Zh, g_Zh);     cudaGetSymbolAddress((void**)&Zlo, g_Zlo);
    cudaGetSymbolAddress((void**)&lath, g_lath); cudaGetSymbolAddress((void**)&latl, g_latl);
    cudaGetSymbolAddress((void**)&latTh, g_latTh); cudaGetSymbolAddress((void**)&latTl, g_latTl);
    cudaGetSymbolAddress((void**)&Ghb, g_Gh);
    cudaGetSymbolAddress((void**)&l2Th, g_l2Th);

    cudaFuncSetAttribute(mma_gemm<0,1>, cudaFuncAttributeMaxDynamicSharedMemorySize, G_SMEM);
    cudaFuncSetAttribute(mma_gemm<1,1>, cudaFuncAttributeMaxDynamicSharedMemorySize, G_SMEM);
    cudaFuncSetAttribute(mma_gemm<2,1>, cudaFuncAttributeMaxDynamicSharedMemorySize, G_SMEM);
    cudaFuncSetAttribute(mma_gemm<3,2>, cudaFuncAttributeMaxDynamicSharedMemorySize, G_SMEM);
    cudaFuncSetAttribute(mma_gemm<7,1>, cudaFuncAttributeMaxDynamicSharedMemorySize, G_SMEM);

    const long FEAT = (long)CCH * HWD;
    dim3 blk(256);

    // 0) splits: v2l hi-only (B-side), l2v hi+lo (A-side), wv hi+lo, wl hi-only
    k_split<<<8192, blk>>>((const float4*)v2l, (uint2*)v2lh, nullptr, (int)(BATCH*FEAT/4));
    k_split<<<8192, blk>>>((const float4*)l2v, (uint2*)l2vh, (uint2*)l2vl, (int)(BATCH*FEAT/4));
    k_split<<<256, blk>>>((const float4*)wv, (uint2*)wvh, (uint2*)wvl, DD*HWD/4);
    k_split<<<256, blk>>>((const float4*)wl, (uint2*)wlh, nullptr, DD*HWD/4);

    // 1) Yv = relu(bn(Wv . V^T))  M=256 N=2048 K=1024
    {
        GArgs a = { wvh, wvl, v2lh, nullptr, nullptr, nullptr,
                    Yv, nullptr, gv, bv, 0, FEAT, (long)DD*CCH, HWD, HWD, CCH, HWD };
        mma_gemm<1,1><<<dim3(CCH/128, DD/128, BATCH), blk, G_SMEM>>>(a);
    }
    // 2) Zl = relu(bn(Xl . Wl^T)) M=2048 N=256 K=1024
    {
        GArgs a = { l2vh, l2vl, wlh, nullptr, nullptr, nullptr,
                    Zl, nullptr, gl, bl, FEAT, 0, (long)CCH*DD, HWD, HWD, DD, HWD };
        mma_gemm<2,1><<<dim3(DD/128, CCH/128, BATCH), blk, G_SMEM>>>(a);
    }
    // 3) norm Yv rows -> split E/O
    k_norm_v2l<<<BATCH*DD, blk>>>((const float4*)Yv,
        (uint32_t*)Eh, (uint32_t*)El, (uint32_t*)Oh, (uint32_t*)Ol);
    // 4) norm Zl rows -> split Zh/Zlo
    k_norm_rows<<<BATCH*CCH, 128>>>(Zl, (uint32_t*)Zh, (uint32_t*)Zlo);
    // 5) lat = E.Vlow^T + O.Vhigh^T  M=256 N=1024 K=1024x2 -> split fp16 out
    {
        GArgs a = { Eh, El, v2lh, Oh, Ol, v2lh + (long)HWD*HWD,
                    lath, latl, nullptr, nullptr,
                    (long)DD*HWD, FEAT, (long)DD*HWD, HWD, HWD, HWD, HWD };
        mma_gemm<3,2><<<dim3(HWD/128, DD/128, BATCH), blk, G_SMEM>>>(a);
    }
    // 6) transpose lat -> latT
    k_transpose<<<dim3(32, 8, BATCH), blk>>>(
        (const uint32_t*)lath, (const uint32_t*)latl, (uint32_t*)latTh, (uint32_t*)latTl);
    // 7) latent row inverse norms
    k_latnorm<<<BATCH*DD, blk>>>((const uint32_t*)lath, (const uint32_t*)latl, invr);
    // 8) G = lat . lat^T  M=N=256 K=1024 (fp32 out)
    {
        GArgs a = { lath, latl, lath, nullptr, nullptr, nullptr,
                    G, nullptr, nullptr, nullptr,
                    (long)DD*HWD, (long)DD*HWD, (long)DD*DD, HWD, HWD, DD, HWD };
        mma_gemm<0,1><<<dim3(DD/128, DD/128, BATCH), blk, G_SMEM>>>(a);
    }
    // 9) aff = softmax(G * invr_d * invr_e) -> fp16 hi only
    k_softmax<<<BATCH*DD, blk>>>(G, invr, (uint32_t*)Ghb);
    // 10) l2T = latT . aff^T  M=1024 N=256 K=256 -> fp16 hi only
    {
        GArgs a = { latTh, latTl, Ghb, nullptr, nullptr, nullptr,
                    l2Th, nullptr, nullptr, nullptr,
                    (long)HWD*DD, (long)DD*DD, (long)HWD*DD, DD, DD, DD, DD };
        mma_gemm<7,1><<<dim3(DD/128, HWD/128, BATCH), blk, G_SMEM>>>(a);
    }
    // 11) out = Zl_adj . l2T^T  M=2048 N=1024 K=256 (fp32 out)
    {
        GArgs a = { Zh, Zlo, l2Th, nullptr, nullptr, nullptr,
                    out, nullptr, nullptr, nullptr,
                    (long)CCH*DD, (long)HWD*DD, (long)CCH*HWD, DD, DD, HWD, DD };
        mma_gemm<0,1><<<dim3(HWD/128, CCH/128, BATCH), blk, G_SMEM>>>(a);
    }
}

// round 13
// speedup vs baseline: 1.5634x; 1.1698x over previous
#include <cuda_runtime.h>
#include <cuda_fp16.h>
#include <math.h>
#include <stdint.h>

#define BATCH 16
#define CCH   2048
#define HWD   1024
#define DD    256
#define BN_RS 0.9999950000374997f   // 1/sqrt(1 + 1e-5)

// ---------------- scratch (device globals; no allocation) ----------------
__device__ __align__(16) float d_Yv [BATCH * DD  * CCH];
__device__ __align__(16) float d_Zl [BATCH * CCH * DD ];
__device__ __align__(16) float d_G  [BATCH * DD  * DD ];
__device__ float d_invr[BATCH * DD];

// fp16 split storage (lo only where needed for accuracy-critical A-sides)
__device__ __align__(16) __half g_v2lh[BATCH*CCH*HWD];                      // hi only
__device__ __align__(16) __half g_l2vh[BATCH*CCH*HWD];                      // hi only
__device__ __align__(16) __half g_wvh[DD*HWD], g_wvl[DD*HWD];
__device__ __align__(16) __half g_wlh[DD*HWD];                              // hi only
__device__ __align__(16) __half g_Eh[BATCH*DD*HWD], g_El[BATCH*DD*HWD];
__device__ __align__(16) __half g_Oh[BATCH*DD*HWD], g_Ol[BATCH*DD*HWD];
__device__ __align__(16) __half g_Zh[BATCH*CCH*DD];                         // hi only
__device__ __align__(16) __half g_lath[BATCH*DD*HWD], g_latl[BATCH*DD*HWD];
__device__ __align__(16) __half g_latTh[BATCH*HWD*DD], g_latTl[BATCH*HWD*DD];
__device__ __align__(16) __half g_Gh[BATCH*DD*DD];                          // hi only
__device__ __align__(16) __half g_l2Th[BATCH*HWD*DD];                       // hi only

// ---------------- helpers ----------------
__device__ __forceinline__ uint32_t cvta_s(const void* p){
    return (uint32_t)__cvta_generic_to_shared(p);
}
__device__ __forceinline__ void cpa16(uint32_t d, const void* s){
    asm volatile("cp.async.cg.shared.global [%0], [%1], 16;" :: "r"(d), "l"(s));
}
#define CP_COMMIT() asm volatile("cp.async.commit_group;")
#define CP_WAIT2()  asm volatile("cp.async.wait_group 2;")

#define LDSM4(R, addr) \
    asm volatile("ldmatrix.sync.aligned.m8n8.x4.shared.b16 {%0,%1,%2,%3}, [%4];" \
        : "=r"((R)[0]), "=r"((R)[1]), "=r"((R)[2]), "=r"((R)[3]) : "r"(addr))

#define MMA16816(d, A, b0, b1) \
    asm volatile("mma.sync.aligned.m16n8k16.row.col.f32.f16.f16.f32 " \
        "{%0,%1,%2,%3}, {%4,%5,%6,%7}, {%8,%9}, {%0,%1,%2,%3};" \
        : "+f"((d)[0]), "+f"((d)[1]), "+f"((d)[2]), "+f"((d)[3]) \
        : "r"((A)[0]), "r"((A)[1]), "r"((A)[2]), "r"((A)[3]), "r"(b0), "r"(b1))

__device__ __forceinline__ uint32_t packh(float x, float y){
    __half2 h = __floats2half2_rn(x, y);
    return *(uint32_t*)&h;
}
__device__ __forceinline__ uint32_t packl(float x, float y){
    float lx = x - __half2float(__float2half_rn(x));
    float ly = y - __half2float(__float2half_rn(y));
    return packh(lx, ly);
}
__device__ __forceinline__ void split16h(float4 v, uint2& hi, uint2& lo){
    hi.x = packh(v.x, v.y); hi.y = packh(v.z, v.w);
    lo.x = packl(v.x, v.y); lo.y = packl(v.z, v.w);
}

// ---------------- fp16 NT GEMM, cp.async 4-stage, 2 CTA/SM ----------------
// D[m,n] = sum_p sum_k A_p[m,k]*B_p[n,k]
// TWO=1: two passes (Ah*Bh + Al*Bh); TWO=0: single pass (Ah*Bh)
// EPI: 0 fp32; 1 BN+ReLU row; 2 BN+ReLU col; 3 split fp16 (C,C2); 7 fp16 hi only
struct GArgs {
    const __half *A0h, *A0l, *B0h;
    const __half *A1h, *A1l, *B1h;
    void *C, *C2;
    const float *gs, *bs;
    long sA, sB, sC;
    int lda, ldb, ldc, K;
};

// TWO=1 stage 24KB: Ah@0, Al@8K, Bh@16K. TWO=0 stage 16KB: Ah@0, Bh@8K.
template<int EPI, int NP, int TWO>
__global__ void __launch_bounds__(256, 2) mma_gemm(GArgs a)
{
    constexpr uint32_t STG = TWO ? 24576u : 16384u;
    constexpr uint32_t BOF = TWO ? 16384u : 8192u;
    extern __shared__ __align__(128) char smem[];
    const int tid = threadIdx.x, w = tid >> 5, lane = tid & 31;
    const int bn0 = blockIdx.x << 7, bm0 = blockIdx.y << 7, b = blockIdx.z;
    const int KS = a.K >> 5;
    const int NS = KS * NP;
    const uint32_t sbase = cvta_s(smem);
    const int wm = w >> 2, wn = w & 3;

    const int r0 = tid >> 2, ch = tid & 3;
    const uint32_t q16 = (uint32_t)((ch ^ ((r0 >> 1) & 3)) * 16);

    auto issue = [&](int s){
        if (s >= NS) return;
        int p = (NP == 2 && s >= KS) ? 1 : 0;
        long k0 = (long)(s - p * KS) * 32;
        uint32_t dst0 = sbase + (uint32_t)(s & 3) * STG + (uint32_t)r0 * 64u + q16;
        {
            const __half* sp = (p ? a.A1h : a.A0h) + (long)b * a.sA + (long)bm0 * a.lda + k0
                             + (long)r0 * a.lda + ch * 8;
            cpa16(dst0,        sp);
            cpa16(dst0 + 4096, sp + 64 * a.lda);
        }
        if (TWO){
            const __half* sp = (p ? a.A1l : a.A0l) + (long)b * a.sA + (long)bm0 * a.lda + k0
                             + (long)r0 * a.lda + ch * 8;
            cpa16(dst0 + 8192,        sp);
            cpa16(dst0 + 8192 + 4096, sp + 64 * a.lda);
        }
        {
            const __half* sp = (p ? a.B1h : a.B0h) + (long)b * a.sB + (long)bn0 * a.ldb + k0
                             + (long)r0 * a.ldb + ch * 8;
            cpa16(dst0 + BOF,        sp);
            cpa16(dst0 + BOF + 4096, sp + 64 * a.ldb);
        }
    };

    float acc[4][4][4];
    #pragma unroll
    for (int i = 0; i < 4; i++)
        #pragma unroll
        for (int j = 0; j < 4; j++)
            #pragma unroll
            for (int t = 0; t < 4; t++) acc[i][j][t] = 0.0f;

    const int aRow = wm * 64 + (lane & 15);
    const uint32_t lqA = (uint32_t)(((lane & 15) >> 1) & 3);
    const uint32_t aC0 = (uint32_t)(lane >> 4);
    const int bRow = wn * 32 + (lane & 7) + ((lane >> 4) & 1) * 8;
    const uint32_t lqB = (uint32_t)(((lane & 7) >> 1) & 3);
    const uint32_t bC0 = (uint32_t)((lane >> 3) & 1);

    issue(0); CP_COMMIT();
    issue(1); CP_COMMIT();
    issue(2); CP_COMMIT();

    for (int i = 0; i < NS; i++){
        CP_WAIT2();
        __syncthreads();
        issue(i + 3);
        CP_COMMIT();

        const uint32_t stb = sbase + (uint32_t)(i & 3) * STG;
        #pragma unroll
        for (int ks = 0; ks < 2; ks++){
            const uint32_t qa = ((aC0 + 2 * ks) ^ lqA) * 16u;
            const uint32_t qb = ((bC0 + 2 * ks) ^ lqB) * 16u;
            uint32_t Afh[4][4], Bfh[2][4];
            #pragma unroll
            for (int mi = 0; mi < 4; mi++){
                uint32_t ad = stb + (uint32_t)(aRow + mi * 16) * 64u + qa;
                LDSM4(Afh[mi], ad);
            }
            #pragma unroll
            for (int nb = 0; nb < 2; nb++){
                uint32_t bd = stb + BOF + (uint32_t)(bRow + nb * 16) * 64u + qb;
                LDSM4(Bfh[nb], bd);
            }
            #pragma unroll
            for (int mi = 0; mi < 4; mi++)
                #pragma unroll
                for (int ni = 0; ni < 4; ni++){
                    int nb = ni >> 1, h = (ni & 1) * 2;
                    MMA16816(acc[mi][ni], Afh[mi], Bfh[nb][h], Bfh[nb][h + 1]);
                }
            if (TWO){
                uint32_t Afl[4][4];
                #pragma unroll
                for (int mi = 0; mi < 4; mi++){
                    uint32_t ad = stb + 8192u + (uint32_t)(aRow + mi * 16) * 64u + qa;
                    LDSM4(Afl[mi], ad);
                }
                #pragma unroll
                for (int mi = 0; mi < 4; mi++)
                    #pragma unroll
                    for (int ni = 0; ni < 4; ni++){
                        int nb = ni >> 1, h = (ni & 1) * 2;
                        MMA16816(acc[mi][ni], Afl[mi], Bfh[nb][h], Bfh[nb][h + 1]);
                    }
            }
        }
    }

    // ---- epilogue
    const int r1 = lane >> 2, cq = (lane & 3) * 2;
    if (EPI == 3 || EPI == 7){
        __half* Ch = (__half*)a.C;
        __half* Cl = (__half*)a.C2;
        const long cb = (long)b * a.sC;
        #pragma unroll
        for (int mi = 0; mi < 4; mi++){
            int m0 = bm0 + wm * 64 + mi * 16 + r1;
            #pragma unroll
            for (int ni = 0; ni < 4; ni++){
                int n = bn0 + wn * 32 + ni * 8 + cq;
                float v0 = acc[mi][ni][0], v1 = acc[mi][ni][1];
                float v2 = acc[mi][ni][2], v3 = acc[mi][ni][3];
                *(uint32_t*)(Ch + cb + (long)m0 * a.ldc + n)       = packh(v0, v1);
                *(uint32_t*)(Ch + cb + (long)(m0 + 8) * a.ldc + n) = packh(v2, v3);
                if (EPI == 3){
                    *(uint32_t*)(Cl + cb + (long)m0 * a.ldc + n)       = packl(v0, v1);
                    *(uint32_t*)(Cl + cb + (long)(m0 + 8) * a.ldc + n) = packl(v2, v3);
                }
            }
        }
    } else {
        float* Cb = (float*)a.C + (long)b * a.sC;
        #pragma unroll
        for (int mi = 0; mi < 4; mi++){
            int m0 = bm0 + wm * 64 + mi * 16 + r1;
            float s0 = 0.f, b0_ = 0.f, s1 = 0.f, b1_ = 0.f;
            if (EPI == 1){
                s0 = a.gs[m0] * BN_RS;     b0_ = a.bs[m0];
                s1 = a.gs[m0 + 8] * BN_RS; b1_ = a.bs[m0 + 8];
            }
            #pragma unroll
            for (int ni = 0; ni < 4; ni++){
                int n = bn0 + wn * 32 + ni * 8 + cq;
                float v0 = acc[mi][ni][0], v1 = acc[mi][ni][1];
                float v2 = acc[mi][ni][2], v3 = acc[mi][ni][3];
                if (EPI == 1){
                    v0 = fmaxf(fmaf(v0, s0, b0_), 0.f); v1 = fmaxf(fmaf(v1, s0, b0_), 0.f);
                    v2 = fmaxf(fmaf(v2, s1, b1_), 0.f); v3 = fmaxf(fmaf(v3, s1, b1_), 0.f);
                } else if (EPI == 2){
                    float gs0 = a.gs[n] * BN_RS, bb0 = a.bs[n];
                    float gs1 = a.gs[n + 1] * BN_RS, bb1 = a.bs[n + 1];
                    v0 = fmaxf(fmaf(v0, gs0, bb0), 0.f); v1 = fmaxf(fmaf(v1, gs1, bb1), 0.f);
                    v2 = fmaxf(fmaf(v2, gs0, bb0), 0.f); v3 = fmaxf(fmaf(v3, gs1, bb1), 0.f);
                }
                *(float2*)(Cb + (long)m0 * a.ldc + n)       = make_float2(v0, v1);
                *(float2*)(Cb + (long)(m0 + 8) * a.ldc + n) = make_float2(v2, v3);
            }
        }
    }
}

#define SMEM_T1 (4 * 24576)
#define SMEM_T0 (4 * 16384)

// ---------------- reductions ----------------
__device__ __forceinline__ float warpSum(float v){
    #pragma unroll
    for (int o = 16; o; o >>= 1) v += __shfl_xor_sync(0xffffffffu, v, o);
    return v;
}
__device__ __forceinline__ float warpMax(float v){
    #pragma unroll
    for (int o = 16; o; o >>= 1) v = fmaxf(v, __shfl_xor_sync(0xffffffffu, v, o));
    return v;
}
__device__ __forceinline__ float blockSum(float v){
    __shared__ float sh[32];
    int w = threadIdx.x >> 5, l = threadIdx.x & 31;
    v = warpSum(v);
    if (l == 0) sh[w] = v;
    __syncthreads();
    int nw = blockDim.x >> 5;
    if (w == 0){ float x = (l < nw) ? sh[l] : 0.0f; x = warpSum(x); if (l == 0) sh[0] = x; }
    __syncthreads();
    float r = sh[0];
    __syncthreads();
    return r;
}
__device__ __forceinline__ float blockMax(float v){
    __shared__ float sh[32];
    int w = threadIdx.x >> 5, l = threadIdx.x & 31;
    v = warpMax(v);
    if (l == 0) sh[w] = v;
    __syncthreads();
    int nw = blockDim.x >> 5;
    if (w == 0){ float x = (l < nw) ? sh[l] : -INFINITY; x = warpMax(x); if (l == 0) sh[0] = x; }
    __syncthreads();
    float r = sh[0];
    __syncthreads();
    return r;
}

// ---------------- elementwise kernels ----------------
__global__ void __launch_bounds__(256)
k_split(const float4* __restrict__ in, uint2* __restrict__ hi, uint2* __restrict__ lo, int n4)
{
    int i = blockIdx.x * blockDim.x + threadIdx.x;
    int stride = gridDim.x * blockDim.x;
    for (; i < n4; i += stride){
        float4 v = in[i];
        uint2 h, l;
        split16h(v, h, l);
        hi[i] = h;
        if (lo) lo[i] = l;
    }
}

__global__ void __launch_bounds__(256)
k_norm_v2l(const float4* __restrict__ Y,
           uint32_t* __restrict__ Eh, uint32_t* __restrict__ El,
           uint32_t* __restrict__ Oh, uint32_t* __restrict__ Ol)
{
    long row = blockIdx.x;
    const float4* y = Y + row * 512;
    int t = threadIdx.x;
    float4 v0 = y[t], v1 = y[t + 256];
    float s = v0.x*v0.x + v0.y*v0.y + v0.z*v0.z + v0.w*v0.w
            + v1.x*v1.x + v1.y*v1.y + v1.z*v1.z + v1.w*v1.w;
    s = blockSum(s);
    float inv = 1.0f / fmaxf(sqrtf(s), 1e-12f);
    long eb = row * 512;
    Eh[eb + t] = packh(v0.x * inv, v0.z * inv);
    El[eb + t] = packl(v0.x * inv, v0.z * inv);
    Oh[eb + t] = packh(v0.y * inv, v0.w * inv);
    Ol[eb + t] = packl(v0.y * inv, v0.w * inv);
    Eh[eb + t + 256] = packh(v1.x * inv, v1.z * inv);
    El[eb + t + 256] = packl(v1.x * inv, v1.z * inv);
    Oh[eb + t + 256] = packh(v1.y * inv, v1.w * inv);
    Ol[eb + t + 256] = packl(v1.y * inv, v1.w * inv);
}

// normalize Zl rows over D=256, write fp16 hi only
__global__ void __launch_bounds__(128)
k_norm_rows(const float* __restrict__ Z, uint32_t* __restrict__ Zh)
{
    long row = blockIdx.x;
    const float2* z = (const float2*)(Z + row * 256);
    int t = threadIdx.x;
    float2 v = z[t];
    float s = blockSum(v.x * v.x + v.y * v.y);
    float inv = 1.0f / fmaxf(sqrtf(s), 1e-12f);
    Zh[row * 128 + t] = packh(v.x * inv, v.y * inv);
}

__global__ void __launch_bounds__(256)
k_transpose(const uint32_t* __restrict__ sH, const uint32_t* __restrict__ sL,
            uint32_t* __restrict__ dH, uint32_t* __restrict__ dL)
{
    __shared__ unsigned short tile[32][34];
    const int b = blockIdx.z, h0 = blockIdx.x * 32, d0 = blockIdx.y * 32;
    const int t = threadIdx.x;
    const uint32_t* srcs[2] = {sH, sL};
    uint32_t* dsts[2] = {dH, dL};
    #pragma unroll
    for (int m = 0; m < 2; m++){
        #pragma unroll
        for (int i = 0; i < 2; i++){
            int s = t + i * 256;
            int d = s >> 4, hu = s & 15;
            uint32_t v = srcs[m][(long)(b * 256 + d0 + d) * 512 + (h0 >> 1) + hu];
            tile[d][2 * hu]     = (unsigned short)(v & 0xFFFFu);
            tile[d][2 * hu + 1] = (unsigned short)(v >> 16);
        }
        __syncthreads();
        #pragma unroll
        for (int i = 0; i < 2; i++){
            int s = t + i * 256;
            int h = s >> 4, du = s & 15;
            uint32_t v = (uint32_t)tile[2 * du][h] | ((uint32_t)tile[2 * du + 1][h] << 16);
            dsts[m][(long)(b * 1024 + h0 + h) * 128 + (d0 >> 1) + du] = v;
        }
        __syncthreads();
    }
}

__global__ void __launch_bounds__(256)
k_latnorm(const uint32_t* __restrict__ H, const uint32_t* __restrict__ L, float* __restrict__ R)
{
    long row = blockIdx.x;
    long base = row * 512;
    int t = threadIdx.x;
    float s = 0.0f;
    #pragma unroll
    for (int i = 0; i < 2; i++){
        long idx = base + t + i * 256;
        uint32_t uh = H[idx], ul = L[idx];
        float2 fh = __half22float2(*(__half2*)&uh);
        float2 fl = __half22float2(*(__half2*)&ul);
        float v0 = fh.x + fl.x, v1 = fh.y + fl.y;
        s += v0 * v0 + v1 * v1;
    }
    s = blockSum(s);
    if (t == 0) R[row] = 1.0f / fmaxf(sqrtf(s), 1e-12f);
}

__global__ void __launch_bounds__(256)
k_softmax(const float* __restrict__ G, const float* __restrict__ R,
          uint32_t* __restrict__ Gh)
{
    long row = blockIdx.x;
    long bb = row >> 8;
    int t = threadIdx.x;
    float ri = R[row];
    float re = R[(bb << 8) + t];
    float x = G[row * 256 + t] * ri * re;
    float mx = blockMax(x);
    float p = expf(x - mx);
    float sm = blockSum(p);
    float g = p / sm;
    float gn = __shfl_down_sync(0xffffffffu, g, 1);
    if ((t & 1) == 0){
        Gh[row * 128 + (t >> 1)] = packh(g, gn);
    }
}

// ---------------- launch ----------------
extern "C" void kernel_launch(void* const* d_in, const int* in_sizes, int n_in,
                              void* d_out, int out_size)
{
    const float* v2l = (const float*)d_in[0];
    const float* l2v = (const float*)d_in[1];
    const float* wv  = (const float*)d_in[2];
    const float* gv  = (const float*)d_in[3];
    const float* bv  = (const float*)d_in[4];
    const float* wl  = (const float*)d_in[5];
    const float* gl  = (const float*)d_in[6];
    const float* bl  = (const float*)d_in[7];
    float* out = (float*)d_out;

    float *Yv, *Zl, *G, *invr;
    __half *v2lh, *l2vh, *wvh, *wvl, *wlh;
    __half *Eh, *El, *Oh, *Ol, *Zh, *lath, *latl, *latTh, *latTl;
    __half *Ghb, *l2Th;
    cudaGetSymbolAddress((void**)&Yv, d_Yv);
    cudaGetSymbolAddress((void**)&Zl, d_Zl);
    cudaGetSymbolAddress((void**)&G, d_G);
    cudaGetSymbolAddress((void**)&invr, d_invr);
    cudaGetSymbolAddress((void**)&v2lh, g_v2lh);
    cudaGetSymbolAddress((void**)&l2vh, g_l2vh);
    cudaGetSymbolAddress((void**)&wvh, g_wvh);   cudaGetSymbolAddress((void**)&wvl, g_wvl);
    cudaGetSymbolAddress((void**)&wlh, g_wlh);
    cudaGetSymbolAddress((void**)&Eh, g_Eh);     cudaGetSymbolAddress((void**)&El, g_El);
    cudaGetSymbolAddress((void**)&Oh, g_Oh);     cudaGetSymbolAddress((void**)&Ol, g_Ol);
    cudaGetSymbolAddress((void**)&Zh, g_Zh);
    cudaGetSymbolAddress((void**)&lath, g_lath); cudaGetSymbolAddress((void**)&latl, g_latl);
    cudaGetSymbolAddress((void**)&latTh, g_latTh); cudaGetSymbolAddress((void**)&latTl, g_latTl);
    cudaGetSymbolAddress((void**)&Ghb, g_Gh);
    cudaGetSymbolAddress((void**)&l2Th, g_l2Th);

    cudaFuncSetAttribute(mma_gemm<0,1,1>, cudaFuncAttributeMaxDynamicSharedMemorySize, SMEM_T1);
    cudaFuncSetAttribute(mma_gemm<1,1,1>, cudaFuncAttributeMaxDynamicSharedMemorySize, SMEM_T1);
    cudaFuncSetAttribute(mma_gemm<2,1,0>, cudaFuncAttributeMaxDynamicSharedMemorySize, SMEM_T0);
    cudaFuncSetAttribute(mma_gemm<3,2,1>, cudaFuncAttributeMaxDynamicSharedMemorySize, SMEM_T1);
    cudaFuncSetAttribute(mma_gemm<7,1,1>, cudaFuncAttributeMaxDynamicSharedMemorySize, SMEM_T1);
    cudaFuncSetAttribute(mma_gemm<0,1,0>, cudaFuncAttributeMaxDynamicSharedMemorySize, SMEM_T0);

    const long FEAT = (long)CCH * HWD;
    dim3 blk(256);

    // 0) splits: v2l hi, l2v hi, wv hi+lo, wl hi
    k_split<<<8192, blk>>>((const float4*)v2l, (uint2*)v2lh, nullptr, (int)(BATCH*FEAT/4));
    k_split<<<8192, blk>>>((const float4*)l2v, (uint2*)l2vh, nullptr, (int)(BATCH*FEAT/4));
    k_split<<<256, blk>>>((const float4*)wv, (uint2*)wvh, (uint2*)wvl, DD*HWD/4);
    k_split<<<256, blk>>>((const float4*)wl, (uint2*)wlh, nullptr, DD*HWD/4);

    // 1) Yv = relu(bn(Wv . V^T))  M=256 N=2048 K=1024  (2-pass)
    {
        GArgs a = { wvh, wvl, v2lh, nullptr, nullptr, nullptr,
                    Yv, nullptr, gv, bv, 0, FEAT, (long)DD*CCH, HWD, HWD, CCH, HWD };
        mma_gemm<1,1,1><<<dim3(CCH/128, DD/128, BATCH), blk, SMEM_T1>>>(a);
    }
    // 2) Zl = relu(bn(Xl . Wl^T)) M=2048 N=256 K=1024  (1-pass)
    {
        GArgs a = { l2vh, nullptr, wlh, nullptr, nullptr, nullptr,
                    Zl, nullptr, gl, bl, FEAT, 0, (long)CCH*DD, HWD, HWD, DD, HWD };
        mma_gemm<2,1,0><<<dim3(DD/128, CCH/128, BATCH), blk, SMEM_T0>>>(a);
    }
    // 3) norm Yv rows -> split E/O (hi+lo)
    k_norm_v2l<<<BATCH*DD, blk>>>((const float4*)Yv,
        (uint32_t*)Eh, (uint32_t*)El, (uint32_t*)Oh, (uint32_t*)Ol);
    // 4) norm Zl rows -> Zh (hi only)
    k_norm_rows<<<BATCH*CCH, 128>>>(Zl, (uint32_t*)Zh);
    // 5) lat = E.Vlow^T + O.Vhigh^T  (2-pass) -> split fp16
    {
        GArgs a = { Eh, El, v2lh, Oh, Ol, v2lh + (long)HWD*HWD,
                    lath, latl, nullptr, nullptr,
                    (long)DD*HWD, FEAT, (long)DD*HWD, HWD, HWD, HWD, HWD };
        mma_gemm<3,2,1><<<dim3(HWD/128, DD/128, BATCH), blk, SMEM_T1>>>(a);
    }
    // 6) transpose lat -> latT
    k_transpose<<<dim3(32, 8, BATCH), blk>>>(
        (const uint32_t*)lath, (const uint32_t*)latl, (uint32_t*)latTh, (uint32_t*)latTl);
    // 7) latent row inverse norms
    k_latnorm<<<BATCH*DD, blk>>>((const uint32_t*)lath, (const uint32_t*)latl, invr);
    // 8) G = lat . lat^T  (2-pass, fp32)
    {
        GArgs a = { lath, latl, lath, nullptr, nullptr, nullptr,
                    G, nullptr, nullptr, nullptr,
                    (long)DD*HWD, (long)DD*HWD, (long)DD*DD, HWD, HWD, DD, HWD };
        mma_gemm<0,1,1><<<dim3(DD/128, DD/128, BATCH), blk, SMEM_T1>>>(a);
    }
    // 9) aff = softmax(G * invr_d * invr_e) -> fp16 hi
    k_softmax<<<BATCH*DD, blk>>>(G, invr, (uint32_t*)Ghb);
    // 10) l2T = latT . aff^T  (2-pass) -> fp16 hi
    {
        GArgs a = { latTh, latTl, Ghb, nullptr, nullptr, nullptr,
                    l2Th, nullptr, nullptr, nullptr,
                    (long)HWD*DD, (long)DD*DD, (long)HWD*DD, DD, DD, DD, DD };
        mma_gemm<7,1,1><<<dim3(DD/128, HWD/128, BATCH), blk, SMEM_T1>>>(a);
    }
    // 11) out = Zl_adj . l2T^T  (1-pass, fp32)
    {
        GArgs a = { Zh, nullptr, l2Th, nullptr, nullptr, nullptr,
                    out, nullptr, nullptr, nullptr,
                    (long)CCH*DD, (long)HWD*DD, (long)CCH*HWD, DD, DD, HWD, DD };
        mma_gemm<0,1,0><<<dim3(HWD/128, CCH/128, BATCH), blk, SMEM_T0>>>(a);
    }
}

// round 14
// speedup vs baseline: 1.9205x; 1.2284x over previous
#include <cuda_runtime.h>
#include <cuda_fp16.h>
#include <math.h>
#include <stdint.h>

#define BATCH 16
#define CCH   2048
#define HWD   1024
#define DD    256
#define BN_RS 0.9999950000374997f   // 1/sqrt(1 + 1e-5)

// ---------------- scratch (device globals; no allocation) ----------------
__device__ __align__(16) float d_Yv [BATCH * DD  * CCH];
__device__ __align__(16) float d_Zl [BATCH * CCH * DD ];
__device__ __align__(16) float d_G  [BATCH * DD  * DD ];
__device__ float d_invr[BATCH * DD];

// fp16 storage (lo kept only for the gram's A-side accuracy)
__device__ __align__(16) __half g_v2lh[BATCH*CCH*HWD];
__device__ __align__(16) __half g_l2vh[BATCH*CCH*HWD];
__device__ __align__(16) __half g_wvh[DD*HWD];
__device__ __align__(16) __half g_wlh[DD*HWD];
__device__ __align__(16) __half g_Eh[BATCH*DD*HWD];
__device__ __align__(16) __half g_Oh[BATCH*DD*HWD];
__device__ __align__(16) __half g_Zh[BATCH*CCH*DD];
__device__ __align__(16) __half g_lath[BATCH*DD*HWD], g_latl[BATCH*DD*HWD];
__device__ __align__(16) __half g_latTh[BATCH*HWD*DD];
__device__ __align__(16) __half g_Gh[BATCH*DD*DD];
__device__ __align__(16) __half g_l2Th[BATCH*HWD*DD];

// ---------------- helpers ----------------
__device__ __forceinline__ uint32_t cvta_s(const void* p){
    return (uint32_t)__cvta_generic_to_shared(p);
}
__device__ __forceinline__ void cpa16(uint32_t d, const void* s){
    asm volatile("cp.async.cg.shared.global [%0], [%1], 16;" :: "r"(d), "l"(s));
}
#define CP_COMMIT() asm volatile("cp.async.commit_group;")
#define CP_WAIT2()  asm volatile("cp.async.wait_group 2;")

#define LDSM4(R, addr) \
    asm volatile("ldmatrix.sync.aligned.m8n8.x4.shared.b16 {%0,%1,%2,%3}, [%4];" \
        : "=r"((R)[0]), "=r"((R)[1]), "=r"((R)[2]), "=r"((R)[3]) : "r"(addr))

#define MMA16816(d, A, b0, b1) \
    asm volatile("mma.sync.aligned.m16n8k16.row.col.f32.f16.f16.f32 " \
        "{%0,%1,%2,%3}, {%4,%5,%6,%7}, {%8,%9}, {%0,%1,%2,%3};" \
        : "+f"((d)[0]), "+f"((d)[1]), "+f"((d)[2]), "+f"((d)[3]) \
        : "r"((A)[0]), "r"((A)[1]), "r"((A)[2]), "r"((A)[3]), "r"(b0), "r"(b1))

__device__ __forceinline__ uint32_t packh(float x, float y){
    __half2 h = __floats2half2_rn(x, y);
    return *(uint32_t*)&h;
}
__device__ __forceinline__ uint32_t packl(float x, float y){
    float lx = x - __half2float(__float2half_rn(x));
    float ly = y - __half2float(__float2half_rn(y));
    return packh(lx, ly);
}
__device__ __forceinline__ void split16h(float4 v, uint2& hi, uint2& lo){
    hi.x = packh(v.x, v.y); hi.y = packh(v.z, v.w);
    lo.x = packl(v.x, v.y); lo.y = packl(v.z, v.w);
}

// ---------------- fp16 NT GEMM, cp.async 4-stage, 2 CTA/SM ----------------
// D[m,n] = sum_p sum_k A_p[m,k]*B_p[n,k]
// TWO=1: two passes (Ah*Bh + Al*Bh); TWO=0: single pass
// EPI: 0 fp32; 1 BN+ReLU row; 2 BN+ReLU col; 3 split fp16 (C,C2); 7 fp16 hi only
struct GArgs {
    const __half *A0h, *A0l, *B0h;
    const __half *A1h, *A1l, *B1h;
    void *C, *C2;
    const float *gs, *bs;
    long sA, sB, sC;
    int lda, ldb, ldc, K;
};

template<int EPI, int NP, int TWO>
__global__ void __launch_bounds__(256, 2) mma_gemm(GArgs a)
{
    constexpr uint32_t STG = TWO ? 24576u : 16384u;
    constexpr uint32_t BOF = TWO ? 16384u : 8192u;
    extern __shared__ __align__(128) char smem[];
    const int tid = threadIdx.x, w = tid >> 5, lane = tid & 31;
    const int bn0 = blockIdx.x << 7, bm0 = blockIdx.y << 7, b = blockIdx.z;
    const int KS = a.K >> 5;
    const int NS = KS * NP;
    const uint32_t sbase = cvta_s(smem);
    const int wm = w >> 2, wn = w & 3;

    const int r0 = tid >> 2, ch = tid & 3;
    const uint32_t q16 = (uint32_t)((ch ^ ((r0 >> 1) & 3)) * 16);

    auto issue = [&](int s){
        if (s >= NS) return;
        int p = (NP == 2 && s >= KS) ? 1 : 0;
        long k0 = (long)(s - p * KS) * 32;
        uint32_t dst0 = sbase + (uint32_t)(s & 3) * STG + (uint32_t)r0 * 64u + q16;
        {
            const __half* sp = (p ? a.A1h : a.A0h) + (long)b * a.sA + (long)bm0 * a.lda + k0
                             + (long)r0 * a.lda + ch * 8;
            cpa16(dst0,        sp);
            cpa16(dst0 + 4096, sp + 64 * a.lda);
        }
        if (TWO){
            const __half* sp = (p ? a.A1l : a.A0l) + (long)b * a.sA + (long)bm0 * a.lda + k0
                             + (long)r0 * a.lda + ch * 8;
            cpa16(dst0 + 8192,        sp);
            cpa16(dst0 + 8192 + 4096, sp + 64 * a.lda);
        }
        {
            const __half* sp = (p ? a.B1h : a.B0h) + (long)b * a.sB + (long)bn0 * a.ldb + k0
                             + (long)r0 * a.ldb + ch * 8;
            cpa16(dst0 + BOF,        sp);
            cpa16(dst0 + BOF + 4096, sp + 64 * a.ldb);
        }
    };

    float acc[4][4][4];
    #pragma unroll
    for (int i = 0; i < 4; i++)
        #pragma unroll
        for (int j = 0; j < 4; j++)
            #pragma unroll
            for (int t = 0; t < 4; t++) acc[i][j][t] = 0.0f;

    const int aRow = wm * 64 + (lane & 15);
    const uint32_t lqA = (uint32_t)(((lane & 15) >> 1) & 3);
    const uint32_t aC0 = (uint32_t)(lane >> 4);
    const int bRow = wn * 32 + (lane & 7) + ((lane >> 4) & 1) * 8;
    const uint32_t lqB = (uint32_t)(((lane & 7) >> 1) & 3);
    const uint32_t bC0 = (uint32_t)((lane >> 3) & 1);

    issue(0); CP_COMMIT();
    issue(1); CP_COMMIT();
    issue(2); CP_COMMIT();

    for (int i = 0; i < NS; i++){
        CP_WAIT2();
        __syncthreads();
        issue(i + 3);
        CP_COMMIT();

        const uint32_t stb = sbase + (uint32_t)(i & 3) * STG;
        #pragma unroll
        for (int ks = 0; ks < 2; ks++){
            const uint32_t qa = ((aC0 + 2 * ks) ^ lqA) * 16u;
            const uint32_t qb = ((bC0 + 2 * ks) ^ lqB) * 16u;
            uint32_t Afh[4][4], Bfh[2][4];
            #pragma unroll
            for (int mi = 0; mi < 4; mi++){
                uint32_t ad = stb + (uint32_t)(aRow + mi * 16) * 64u + qa;
                LDSM4(Afh[mi], ad);
            }
            #pragma unroll
            for (int nb = 0; nb < 2; nb++){
                uint32_t bd = stb + BOF + (uint32_t)(bRow + nb * 16) * 64u + qb;
                LDSM4(Bfh[nb], bd);
            }
            #pragma unroll
            for (int mi = 0; mi < 4; mi++)
                #pragma unroll
                for (int ni = 0; ni < 4; ni++){
                    int nb = ni >> 1, h = (ni & 1) * 2;
                    MMA16816(acc[mi][ni], Afh[mi], Bfh[nb][h], Bfh[nb][h + 1]);
                }
            if (TWO){
                uint32_t Afl[4][4];
                #pragma unroll
                for (int mi = 0; mi < 4; mi++){
                    uint32_t ad = stb + 8192u + (uint32_t)(aRow + mi * 16) * 64u + qa;
                    LDSM4(Afl[mi], ad);
                }
                #pragma unroll
                for (int mi = 0; mi < 4; mi++)
                    #pragma unroll
                    for (int ni = 0; ni < 4; ni++){
                        int nb = ni >> 1, h = (ni & 1) * 2;
                        MMA16816(acc[mi][ni], Afl[mi], Bfh[nb][h], Bfh[nb][h + 1]);
                    }
            }
        }
    }

    // ---- epilogue
    const int r1 = lane >> 2, cq = (lane & 3) * 2;
    if (EPI == 3 || EPI == 7){
        __half* Ch = (__half*)a.C;
        __half* Cl = (__half*)a.C2;
        const long cb = (long)b * a.sC;
        #pragma unroll
        for (int mi = 0; mi < 4; mi++){
            int m0 = bm0 + wm * 64 + mi * 16 + r1;
            #pragma unroll
            for (int ni = 0; ni < 4; ni++){
                int n = bn0 + wn * 32 + ni * 8 + cq;
                float v0 = acc[mi][ni][0], v1 = acc[mi][ni][1];
                float v2 = acc[mi][ni][2], v3 = acc[mi][ni][3];
                *(uint32_t*)(Ch + cb + (long)m0 * a.ldc + n)       = packh(v0, v1);
                *(uint32_t*)(Ch + cb + (long)(m0 + 8) * a.ldc + n) = packh(v2, v3);
                if (EPI == 3){
                    *(uint32_t*)(Cl + cb + (long)m0 * a.ldc + n)       = packl(v0, v1);
                    *(uint32_t*)(Cl + cb + (long)(m0 + 8) * a.ldc + n) = packl(v2, v3);
                }
            }
        }
    } else {
        float* Cb = (float*)a.C + (long)b * a.sC;
        #pragma unroll
        for (int mi = 0; mi < 4; mi++){
            int m0 = bm0 + wm * 64 + mi * 16 + r1;
            float s0 = 0.f, b0_ = 0.f, s1 = 0.f, b1_ = 0.f;
            if (EPI == 1){
                s0 = a.gs[m0] * BN_RS;     b0_ = a.bs[m0];
                s1 = a.gs[m0 + 8] * BN_RS; b1_ = a.bs[m0 + 8];
            }
            #pragma unroll
            for (int ni = 0; ni < 4; ni++){
                int n = bn0 + wn * 32 + ni * 8 + cq;
                float v0 = acc[mi][ni][0], v1 = acc[mi][ni][1];
                float v2 = acc[mi][ni][2], v3 = acc[mi][ni][3];
                if (EPI == 1){
                    v0 = fmaxf(fmaf(v0, s0, b0_), 0.f); v1 = fmaxf(fmaf(v1, s0, b0_), 0.f);
                    v2 = fmaxf(fmaf(v2, s1, b1_), 0.f); v3 = fmaxf(fmaf(v3, s1, b1_), 0.f);
                } else if (EPI == 2){
                    float gs0 = a.gs[n] * BN_RS, bb0 = a.bs[n];
                    float gs1 = a.gs[n + 1] * BN_RS, bb1 = a.bs[n + 1];
                    v0 = fmaxf(fmaf(v0, gs0, bb0), 0.f); v1 = fmaxf(fmaf(v1, gs1, bb1), 0.f);
                    v2 = fmaxf(fmaf(v2, gs0, bb0), 0.f); v3 = fmaxf(fmaf(v3, gs1, bb1), 0.f);
                }
                *(float2*)(Cb + (long)m0 * a.ldc + n)       = make_float2(v0, v1);
                *(float2*)(Cb + (long)(m0 + 8) * a.ldc + n) = make_float2(v2, v3);
            }
        }
    }
}

#define SMEM_T1 (4 * 24576)
#define SMEM_T0 (4 * 16384)

// ---------------- reductions ----------------
__device__ __forceinline__ float warpSum(float v){
    #pragma unroll
    for (int o = 16; o; o >>= 1) v += __shfl_xor_sync(0xffffffffu, v, o);
    return v;
}
__device__ __forceinline__ float warpMax(float v){
    #pragma unroll
    for (int o = 16; o; o >>= 1) v = fmaxf(v, __shfl_xor_sync(0xffffffffu, v, o));
    return v;
}
__device__ __forceinline__ float blockSum(float v){
    __shared__ float sh[32];
    int w = threadIdx.x >> 5, l = threadIdx.x & 31;
    v = warpSum(v);
    if (l == 0) sh[w] = v;
    __syncthreads();
    int nw = blockDim.x >> 5;
    if (w == 0){ float x = (l < nw) ? sh[l] : 0.0f; x = warpSum(x); if (l == 0) sh[0] = x; }
    __syncthreads();
    float r = sh[0];
    __syncthreads();
    return r;
}
__device__ __forceinline__ float blockMax(float v){
    __shared__ float sh[32];
    int w = threadIdx.x >> 5, l = threadIdx.x & 31;
    v = warpMax(v);
    if (l == 0) sh[w] = v;
    __syncthreads();
    int nw = blockDim.x >> 5;
    if (w == 0){ float x = (l < nw) ? sh[l] : -INFINITY; x = warpMax(x); if (l == 0) sh[0] = x; }
    __syncthreads();
    float r = sh[0];
    __syncthreads();
    return r;
}

// ---------------- elementwise kernels ----------------
__global__ void __launch_bounds__(256)
k_split(const float4* __restrict__ in, uint2* __restrict__ hi, uint2* __restrict__ lo, int n4)
{
    int i = blockIdx.x * blockDim.x + threadIdx.x;
    int stride = gridDim.x * blockDim.x;
    for (; i < n4; i += stride){
        float4 v = in[i];
        uint2 h, l;
        split16h(v, h, l);
        hi[i] = h;
        if (lo) lo[i] = l;
    }
}

// normalize Yv rows over C=2048, deinterleave even/odd, write fp16 hi only
__global__ void __launch_bounds__(256)
k_norm_v2l(const float4* __restrict__ Y,
           uint32_t* __restrict__ Eh, uint32_t* __restrict__ Oh)
{
    long row = blockIdx.x;
    const float4* y = Y + row * 512;
    int t = threadIdx.x;
    float4 v0 = y[t], v1 = y[t + 256];
    float s = v0.x*v0.x + v0.y*v0.y + v0.z*v0.z + v0.w*v0.w
            + v1.x*v1.x + v1.y*v1.y + v1.z*v1.z + v1.w*v1.w;
    s = blockSum(s);
    float inv = 1.0f / fmaxf(sqrtf(s), 1e-12f);
    long eb = row * 512;
    Eh[eb + t] = packh(v0.x * inv, v0.z * inv);
    Oh[eb + t] = packh(v0.y * inv, v0.w * inv);
    Eh[eb + t + 256] = packh(v1.x * inv, v1.z * inv);
    Oh[eb + t + 256] = packh(v1.y * inv, v1.w * inv);
}

// normalize Zl rows over D=256, write fp16 hi only
__global__ void __launch_bounds__(128)
k_norm_rows(const float* __restrict__ Z, uint32_t* __restrict__ Zh)
{
    long row = blockIdx.x;
    const float2* z = (const float2*)(Z + row * 256);
    int t = threadIdx.x;
    float2 v = z[t];
    float s = blockSum(v.x * v.x + v.y * v.y);
    float inv = 1.0f / fmaxf(sqrtf(s), 1e-12f);
    Zh[row * 128 + t] = packh(v.x * inv, v.y * inv);
}

// transpose lat hi [b,256,1024] -> latT hi [b,1024,256]
__global__ void __launch_bounds__(256)
k_transpose(const uint32_t* __restrict__ sH, uint32_t* __restrict__ dH)
{
    __shared__ unsigned short tile[32][34];
    const int b = blockIdx.z, h0 = blockIdx.x * 32, d0 = blockIdx.y * 32;
    const int t = threadIdx.x;
    #pragma unroll
    for (int i = 0; i < 2; i++){
        int s = t + i * 256;
        int d = s >> 4, hu = s & 15;
        uint32_t v = sH[(long)(b * 256 + d0 + d) * 512 + (h0 >> 1) + hu];
        tile[d][2 * hu]     = (unsigned short)(v & 0xFFFFu);
        tile[d][2 * hu + 1] = (unsigned short)(v >> 16);
    }
    __syncthreads();
    #pragma unroll
    for (int i = 0; i < 2; i++){
        int s = t + i * 256;
        int h = s >> 4, du = s & 15;
        uint32_t v = (uint32_t)tile[2 * du][h] | ((uint32_t)tile[2 * du + 1][h] << 16);
        dH[(long)(b * 1024 + h0 + h) * 128 + (d0 >> 1) + du] = v;
    }
}

// latent row inverse norms from fp16 hi/lo
__global__ void __launch_bounds__(256)
k_latnorm(const uint32_t* __restrict__ H, const uint32_t* __restrict__ L, float* __restrict__ R)
{
    long row = blockIdx.x;
    long base = row * 512;
    int t = threadIdx.x;
    float s = 0.0f;
    #pragma unroll
    for (int i = 0; i < 2; i++){
        long idx = base + t + i * 256;
        uint32_t uh = H[idx], ul = L[idx];
        float2 fh = __half22float2(*(__half2*)&uh);
        float2 fl = __half22float2(*(__half2*)&ul);
        float v0 = fh.x + fl.x, v1 = fh.y + fl.y;
        s += v0 * v0 + v1 * v1;
    }
    s = blockSum(s);
    if (t == 0) R[row] = 1.0f / fmaxf(sqrtf(s), 1e-12f);
}

__global__ void __launch_bounds__(256)
k_softmax(const float* __restrict__ G, const float* __restrict__ R,
          uint32_t* __restrict__ Gh)
{
    long row = blockIdx.x;
    long bb = row >> 8;
    int t = threadIdx.x;
    float ri = R[row];
    float re = R[(bb << 8) + t];
    float x = G[row * 256 + t] * ri * re;
    float mx = blockMax(x);
    float p = expf(x - mx);
    float sm = blockSum(p);
    float g = p / sm;
    float gn = __shfl_down_sync(0xffffffffu, g, 1);
    if ((t & 1) == 0){
        Gh[row * 128 + (t >> 1)] = packh(g, gn);
    }
}

// ---------------- launch ----------------
extern "C" void kernel_launch(void* const* d_in, const int* in_sizes, int n_in,
                              void* d_out, int out_size)
{
    const float* v2l = (const float*)d_in[0];
    const float* l2v = (const float*)d_in[1];
    const float* wv  = (const float*)d_in[2];
    const float* gv  = (const float*)d_in[3];
    const float* bv  = (const float*)d_in[4];
    const float* wl  = (const float*)d_in[5];
    const float* gl  = (const float*)d_in[6];
    const float* bl  = (const float*)d_in[7];
    float* out = (float*)d_out;

    float *Yv, *Zl, *G, *invr;
    __half *v2lh, *l2vh, *wvh, *wlh;
    __half *Eh, *Oh, *Zh, *lath, *latl, *latTh;
    __half *Ghb, *l2Th;
    cudaGetSymbolAddress((void**)&Yv, d_Yv);
    cudaGetSymbolAddress((void**)&Zl, d_Zl);
    cudaGetSymbolAddress((void**)&G, d_G);
    cudaGetSymbolAddress((void**)&invr, d_invr);
    cudaGetSymbolAddress((void**)&v2lh, g_v2lh);
    cudaGetSymbolAddress((void**)&l2vh, g_l2vh);
    cudaGetSymbolAddress((void**)&wvh, g_wvh);
    cudaGetSymbolAddress((void**)&wlh, g_wlh);
    cudaGetSymbolAddress((void**)&Eh, g_Eh);
    cudaGetSymbolAddress((void**)&Oh, g_Oh);
    cudaGetSymbolAddress((void**)&Zh, g_Zh);
    cudaGetSymbolAddress((void**)&lath, g_lath); cudaGetSymbolAddress((void**)&latl, g_latl);
    cudaGetSymbolAddress((void**)&latTh, g_latTh);
    cudaGetSymbolAddress((void**)&Ghb, g_Gh);
    cudaGetSymbolAddress((void**)&l2Th, g_l2Th);

    cudaFuncSetAttribute(mma_gemm<1,1,0>, cudaFuncAttributeMaxDynamicSharedMemorySize, SMEM_T0);
    cudaFuncSetAttribute(mma_gemm<2,1,0>, cudaFuncAttributeMaxDynamicSharedMemorySize, SMEM_T0);
    cudaFuncSetAttribute(mma_gemm<3,2,0>, cudaFuncAttributeMaxDynamicSharedMemorySize, SMEM_T0);
    cudaFuncSetAttribute(mma_gemm<0,1,1>, cudaFuncAttributeMaxDynamicSharedMemorySize, SMEM_T1);
    cudaFuncSetAttribute(mma_gemm<7,1,0>, cudaFuncAttributeMaxDynamicSharedMemorySize, SMEM_T0);
    cudaFuncSetAttribute(mma_gemm<0,1,0>, cudaFuncAttributeMaxDynamicSharedMemorySize, SMEM_T0);

    const long FEAT = (long)CCH * HWD;
    dim3 blk(256);

    // 0) splits: all hi only
    k_split<<<8192, blk>>>((const float4*)v2l, (uint2*)v2lh, nullptr, (int)(BATCH*FEAT/4));
    k_split<<<8192, blk>>>((const float4*)l2v, (uint2*)l2vh, nullptr, (int)(BATCH*FEAT/4));
    k_split<<<256, blk>>>((const float4*)wv, (uint2*)wvh, nullptr, DD*HWD/4);
    k_split<<<256, blk>>>((const float4*)wl, (uint2*)wlh, nullptr, DD*HWD/4);

    // 1) Yv = relu(bn(Wv . V^T))  (1-pass)
    {
        GArgs a = { wvh, nullptr, v2lh, nullptr, nullptr, nullptr,
                    Yv, nullptr, gv, bv, 0, FEAT, (long)DD*CCH, HWD, HWD, CCH, HWD };
        mma_gemm<1,1,0><<<dim3(CCH/128, DD/128, BATCH), blk, SMEM_T0>>>(a);
    }
    // 2) Zl = relu(bn(Xl . Wl^T))  (1-pass)
    {
        GArgs a = { l2vh, nullptr, wlh, nullptr, nullptr, nullptr,
                    Zl, nullptr, gl, bl, FEAT, 0, (long)CCH*DD, HWD, HWD, DD, HWD };
        mma_gemm<2,1,0><<<dim3(DD/128, CCH/128, BATCH), blk, SMEM_T0>>>(a);
    }
    // 3) norm Yv rows -> E/O hi
    k_norm_v2l<<<BATCH*DD, blk>>>((const float4*)Yv, (uint32_t*)Eh, (uint32_t*)Oh);
    // 4) norm Zl rows -> Zh hi
    k_norm_rows<<<BATCH*CCH, 128>>>(Zl, (uint32_t*)Zh);
    // 5) lat = E.Vlow^T + O.Vhigh^T  (1-pass) -> split fp16 hi+lo
    {
        GArgs a = { Eh, nullptr, v2lh, Oh, nullptr, v2lh + (long)HWD*HWD,
                    lath, latl, nullptr, nullptr,
                    (long)DD*HWD, FEAT, (long)DD*HWD, HWD, HWD, HWD, HWD };
        mma_gemm<3,2,0><<<dim3(HWD/128, DD/128, BATCH), blk, SMEM_T0>>>(a);
    }
    // 6) transpose lat hi -> latT hi
    k_transpose<<<dim3(32, 8, BATCH), blk>>>((const uint32_t*)lath, (uint32_t*)latTh);
    // 7) latent row inverse norms
    k_latnorm<<<BATCH*DD, blk>>>((const uint32_t*)lath, (const uint32_t*)latl, invr);
    // 8) G = lat . lat^T  (2-pass, fp32) — insurance for softmax input
    {
        GArgs a = { lath, latl, lath, nullptr, nullptr, nullptr,
                    G, nullptr, nullptr, nullptr,
                    (long)DD*HWD, (long)DD*HWD, (long)DD*DD, HWD, HWD, DD, HWD };
        mma_gemm<0,1,1><<<dim3(DD/128, DD/128, BATCH), blk, SMEM_T1>>>(a);
    }
    // 9) aff = softmax(G * invr_d * invr_e) -> fp16 hi
    k_softmax<<<BATCH*DD, blk>>>(G, invr, (uint32_t*)Ghb);
    // 10) l2T = latT . aff^T  (1-pass) -> fp16 hi
    {
        GArgs a = { latTh, nullptr, Ghb, nullptr, nullptr, nullptr,
                    l2Th, nullptr, nullptr, nullptr,
                    (long)HWD*DD, (long)DD*DD, (long)HWD*DD, DD, DD, DD, DD };
        mma_gemm<7,1,0><<<dim3(DD/128, HWD/128, BATCH), blk, SMEM_T0>>>(a);
    }
    // 11) out = Zl_adj . l2T^T  (1-pass, fp32)
    {
        GArgs a = { Zh, nullptr, l2Th, nullptr, nullptr, nullptr,
                    out, nullptr, nullptr, nullptr,
                    (long)CCH*DD, (long)HWD*DD, (long)CCH*HWD, DD, DD, HWD, DD };
        mma_gemm<0,1,0><<<dim3(HWD/128, CCH/128, BATCH), blk, SMEM_T0>>>(a);
    }
}

// round 15
// speedup vs baseline: 2.0363x; 1.0603x over previous
#include <cuda_runtime.h>
#include <cuda_fp16.h>
#include <math.h>
#include <stdint.h>

#define BATCH 16
#define CCH   2048
#define HWD   1024
#define DD    256
#define BN_RS 0.9999950000374997f   // 1/sqrt(1 + 1e-5)

// ---------------- scratch (device globals; no allocation) ----------------
__device__ __align__(16) float d_G  [BATCH * DD * DD];
__device__ float d_invr[BATCH * DD];

__device__ __align__(16) __half g_v2lh[BATCH*CCH*HWD];
__device__ __align__(16) __half g_l2vh[BATCH*CCH*HWD];
__device__ __align__(16) __half g_wvh[DD*HWD];
__device__ __align__(16) __half g_wlh[DD*HWD];
__device__ __align__(16) __half g_Yvh[BATCH*DD*CCH];     // psi_v fp16
__device__ __align__(16) __half g_Zlh[BATCH*CCH*DD];     // psi_l fp16 (pre-norm)
__device__ __align__(16) __half g_Eh[BATCH*DD*HWD];
__device__ __align__(16) __half g_Oh[BATCH*DD*HWD];
__device__ __align__(16) __half g_Zh[BATCH*CCH*DD];
__device__ __align__(16) __half g_lath[BATCH*DD*HWD];
__device__ __align__(16) __half g_latTh[BATCH*HWD*DD];
__device__ __align__(16) __half g_Gh[BATCH*DD*DD];
__device__ __align__(16) __half g_l2Th[BATCH*HWD*DD];

// ---------------- helpers ----------------
__device__ __forceinline__ uint32_t cvta_s(const void* p){
    return (uint32_t)__cvta_generic_to_shared(p);
}
__device__ __forceinline__ void cpa16(uint32_t d, const void* s){
    asm volatile("cp.async.cg.shared.global [%0], [%1], 16;" :: "r"(d), "l"(s));
}
#define CP_COMMIT() asm volatile("cp.async.commit_group;")
#define CP_WAIT2()  asm volatile("cp.async.wait_group 2;")

#define LDSM4(R, addr) \
    asm volatile("ldmatrix.sync.aligned.m8n8.x4.shared.b16 {%0,%1,%2,%3}, [%4];" \
        : "=r"((R)[0]), "=r"((R)[1]), "=r"((R)[2]), "=r"((R)[3]) : "r"(addr))

#define MMA16816(d, A, b0, b1) \
    asm volatile("mma.sync.aligned.m16n8k16.row.col.f32.f16.f16.f32 " \
        "{%0,%1,%2,%3}, {%4,%5,%6,%7}, {%8,%9}, {%0,%1,%2,%3};" \
        : "+f"((d)[0]), "+f"((d)[1]), "+f"((d)[2]), "+f"((d)[3]) \
        : "r"((A)[0]), "r"((A)[1]), "r"((A)[2]), "r"((A)[3]), "r"(b0), "r"(b1))

__device__ __forceinline__ uint32_t packh(float x, float y){
    __half2 h = __floats2half2_rn(x, y);
    return *(uint32_t*)&h;
}
__device__ __forceinline__ uint32_t packl(float x, float y){
    float lx = x - __half2float(__float2half_rn(x));
    float ly = y - __half2float(__float2half_rn(y));
    return packh(lx, ly);
}
__device__ __forceinline__ void split16h(float4 v, uint2& hi){
    hi.x = packh(v.x, v.y); hi.y = packh(v.z, v.w);
}

// ---------------- fp16 NT GEMM, cp.async 4-stage, 2 CTA/SM ----------------
// D[m,n] = sum_p sum_k A_p[m,k]*B_p[n,k]
// TWO=1: + Al*Bh pass. EPI: 0 fp32; 7 fp16 hi; 8 BN+ReLU row -> fp16;
//        9 BN+ReLU col -> fp16
struct GArgs {
    const __half *A0h, *A0l, *B0h;
    const __half *A1h, *A1l, *B1h;
    void *C, *C2;
    const float *gs, *bs;
    long sA, sB, sC;
    int lda, ldb, ldc, K;
};

template<int EPI, int NP, int TWO>
__global__ void __launch_bounds__(256, 2) mma_gemm(GArgs a)
{
    constexpr uint32_t STG = TWO ? 24576u : 16384u;
    constexpr uint32_t BOF = TWO ? 16384u : 8192u;
    extern __shared__ __align__(128) char smem[];
    const int tid = threadIdx.x, w = tid >> 5, lane = tid & 31;
    const int bn0 = blockIdx.x << 7, bm0 = blockIdx.y << 7, b = blockIdx.z;
    const int KS = a.K >> 5;
    const int NS = KS * NP;
    const uint32_t sbase = cvta_s(smem);
    const int wm = w >> 2, wn = w & 3;

    const int r0 = tid >> 2, ch = tid & 3;
    const uint32_t q16 = (uint32_t)((ch ^ ((r0 >> 1) & 3)) * 16);

    auto issue = [&](int s){
        if (s >= NS) return;
        int p = (NP == 2 && s >= KS) ? 1 : 0;
        long k0 = (long)(s - p * KS) * 32;
        uint32_t dst0 = sbase + (uint32_t)(s & 3) * STG + (uint32_t)r0 * 64u + q16;
        {
            const __half* sp = (p ? a.A1h : a.A0h) + (long)b * a.sA + (long)bm0 * a.lda + k0
                             + (long)r0 * a.lda + ch * 8;
            cpa16(dst0,        sp);
            cpa16(dst0 + 4096, sp + 64 * a.lda);
        }
        if (TWO){
            const __half* sp = (p ? a.A1l : a.A0l) + (long)b * a.sA + (long)bm0 * a.lda + k0
                             + (long)r0 * a.lda + ch * 8;
            cpa16(dst0 + 8192,        sp);
            cpa16(dst0 + 8192 + 4096, sp + 64 * a.lda);
        }
        {
            const __half* sp = (p ? a.B1h : a.B0h) + (long)b * a.sB + (long)bn0 * a.ldb + k0
                             + (long)r0 * a.ldb + ch * 8;
            cpa16(dst0 + BOF,        sp);
            cpa16(dst0 + BOF + 4096, sp + 64 * a.ldb);
        }
    };

    float acc[4][4][4];
    #pragma unroll
    for (int i = 0; i < 4; i++)
        #pragma unroll
        for (int j = 0; j < 4; j++)
            #pragma unroll
            for (int t = 0; t < 4; t++) acc[i][j][t] = 0.0f;

    const int aRow = wm * 64 + (lane & 15);
    const uint32_t lqA = (uint32_t)(((lane & 15) >> 1) & 3);
    const uint32_t aC0 = (uint32_t)(lane >> 4);
    const int bRow = wn * 32 + (lane & 7) + ((lane >> 4) & 1) * 8;
    const uint32_t lqB = (uint32_t)(((lane & 7) >> 1) & 3);
    const uint32_t bC0 = (uint32_t)((lane >> 3) & 1);

    issue(0); CP_COMMIT();
    issue(1); CP_COMMIT();
    issue(2); CP_COMMIT();

    for (int i = 0; i < NS; i++){
        CP_WAIT2();
        __syncthreads();
        issue(i + 3);
        CP_COMMIT();

        const uint32_t stb = sbase + (uint32_t)(i & 3) * STG;
        #pragma unroll
        for (int ks = 0; ks < 2; ks++){
            const uint32_t qa = ((aC0 + 2 * ks) ^ lqA) * 16u;
            const uint32_t qb = ((bC0 + 2 * ks) ^ lqB) * 16u;
            uint32_t Afh[4][4], Bfh[2][4];
            #pragma unroll
            for (int mi = 0; mi < 4; mi++){
                uint32_t ad = stb + (uint32_t)(aRow + mi * 16) * 64u + qa;
                LDSM4(Afh[mi], ad);
            }
            #pragma unroll
            for (int nb = 0; nb < 2; nb++){
                uint32_t bd = stb + BOF + (uint32_t)(bRow + nb * 16) * 64u + qb;
                LDSM4(Bfh[nb], bd);
            }
            #pragma unroll
            for (int mi = 0; mi < 4; mi++)
                #pragma unroll
                for (int ni = 0; ni < 4; ni++){
                    int nb = ni >> 1, h = (ni & 1) * 2;
                    MMA16816(acc[mi][ni], Afh[mi], Bfh[nb][h], Bfh[nb][h + 1]);
                }
            if (TWO){
                uint32_t Afl[4][4];
                #pragma unroll
                for (int mi = 0; mi < 4; mi++){
                    uint32_t ad = stb + 8192u + (uint32_t)(aRow + mi * 16) * 64u + qa;
                    LDSM4(Afl[mi], ad);
                }
                #pragma unroll
                for (int mi = 0; mi < 4; mi++)
                    #pragma unroll
                    for (int ni = 0; ni < 4; ni++){
                        int nb = ni >> 1, h = (ni & 1) * 2;
                        MMA16816(acc[mi][ni], Afl[mi], Bfh[nb][h], Bfh[nb][h + 1]);
                    }
            }
        }
    }

    // ---- epilogue
    const int r1 = lane >> 2, cq = (lane & 3) * 2;
    if (EPI == 7 || EPI == 8 || EPI == 9){
        __half* Ch = (__half*)a.C;
        const long cb = (long)b * a.sC;
        #pragma unroll
        for (int mi = 0; mi < 4; mi++){
            int m0 = bm0 + wm * 64 + mi * 16 + r1;
            float s0 = 0.f, b0_ = 0.f, s1 = 0.f, b1_ = 0.f;
            if (EPI == 8){
                s0 = a.gs[m0] * BN_RS;     b0_ = a.bs[m0];
                s1 = a.gs[m0 + 8] * BN_RS; b1_ = a.bs[m0 + 8];
            }
            #pragma unroll
            for (int ni = 0; ni < 4; ni++){
                int n = bn0 + wn * 32 + ni * 8 + cq;
                float v0 = acc[mi][ni][0], v1 = acc[mi][ni][1];
                float v2 = acc[mi][ni][2], v3 = acc[mi][ni][3];
                if (EPI == 8){
                    v0 = fmaxf(fmaf(v0, s0, b0_), 0.f); v1 = fmaxf(fmaf(v1, s0, b0_), 0.f);
                    v2 = fmaxf(fmaf(v2, s1, b1_), 0.f); v3 = fmaxf(fmaf(v3, s1, b1_), 0.f);
                } else if (EPI == 9){
                    float gs0 = a.gs[n] * BN_RS, bb0 = a.bs[n];
                    float gs1 = a.gs[n + 1] * BN_RS, bb1 = a.bs[n + 1];
                    v0 = fmaxf(fmaf(v0, gs0, bb0), 0.f); v1 = fmaxf(fmaf(v1, gs1, bb1), 0.f);
                    v2 = fmaxf(fmaf(v2, gs0, bb0), 0.f); v3 = fmaxf(fmaf(v3, gs1, bb1), 0.f);
                }
                *(uint32_t*)(Ch + cb + (long)m0 * a.ldc + n)       = packh(v0, v1);
                *(uint32_t*)(Ch + cb + (long)(m0 + 8) * a.ldc + n) = packh(v2, v3);
            }
        }
    } else {  // EPI 0: fp32 out
        float* Cb = (float*)a.C + (long)b * a.sC;
        #pragma unroll
        for (int mi = 0; mi < 4; mi++){
            int m0 = bm0 + wm * 64 + mi * 16 + r1;
            #pragma unroll
            for (int ni = 0; ni < 4; ni++){
                int n = bn0 + wn * 32 + ni * 8 + cq;
                *(float2*)(Cb + (long)m0 * a.ldc + n)
                    = make_float2(acc[mi][ni][0], acc[mi][ni][1]);
                *(float2*)(Cb + (long)(m0 + 8) * a.ldc + n)
                    = make_float2(acc[mi][ni][2], acc[mi][ni][3]);
            }
        }
    }
}

#define SMEM_T1 (4 * 24576)
#define SMEM_T0 (4 * 16384)

// ---------------- reductions ----------------
__device__ __forceinline__ float warpSum(float v){
    #pragma unroll
    for (int o = 16; o; o >>= 1) v += __shfl_xor_sync(0xffffffffu, v, o);
    return v;
}
__device__ __forceinline__ float warpMax(float v){
    #pragma unroll
    for (int o = 16; o; o >>= 1) v = fmaxf(v, __shfl_xor_sync(0xffffffffu, v, o));
    return v;
}
__device__ __forceinline__ float blockSum(float v){
    __shared__ float sh[32];
    int w = threadIdx.x >> 5, l = threadIdx.x & 31;
    v = warpSum(v);
    if (l == 0) sh[w] = v;
    __syncthreads();
    int nw = blockDim.x >> 5;
    if (w == 0){ float x = (l < nw) ? sh[l] : 0.0f; x = warpSum(x); if (l == 0) sh[0] = x; }
    __syncthreads();
    float r = sh[0];
    __syncthreads();
    return r;
}
__device__ __forceinline__ float blockMax(float v){
    __shared__ float sh[32];
    int w = threadIdx.x >> 5, l = threadIdx.x & 31;
    v = warpMax(v);
    if (l == 0) sh[w] = v;
    __syncthreads();
    int nw = blockDim.x >> 5;
    if (w == 0){ float x = (l < nw) ? sh[l] : -INFINITY; x = warpMax(x); if (l == 0) sh[0] = x; }
    __syncthreads();
    float r = sh[0];
    __syncthreads();
    return r;
}

// ---------------- elementwise kernels ----------------
__global__ void __launch_bounds__(256)
k_split(const float4* __restrict__ in, uint2* __restrict__ hi, int n4)
{
    int i = blockIdx.x * blockDim.x + threadIdx.x;
    int stride = gridDim.x * blockDim.x;
    for (; i < n4; i += stride){
        float4 v = in[i];
        uint2 h;
        split16h(v, h);
        hi[i] = h;
    }
}

// normalize fp16 Yv rows over C=2048, deinterleave even/odd, write fp16 hi
// uint32 j of a row holds channels (2j, 2j+1) = (E[j], O[j])
__global__ void __launch_bounds__(256)
k_norm_v2l(const uint2* __restrict__ Y,
           uint32_t* __restrict__ Eh, uint32_t* __restrict__ Oh)
{
    long row = blockIdx.x;
    const uint2* y = Y + row * 512;          // 512 uint2 = 1024 uint32 = 2048 halves
    int t = threadIdx.x;
    uint2 u0 = y[t], u1 = y[t + 256];
    float2 a0 = __half22float2(*(__half2*)&u0.x);
    float2 a1 = __half22float2(*(__half2*)&u0.y);
    float2 a2 = __half22float2(*(__half2*)&u1.x);
    float2 a3 = __half22float2(*(__half2*)&u1.y);
    float s = a0.x*a0.x + a0.y*a0.y + a1.x*a1.x + a1.y*a1.y
            + a2.x*a2.x + a2.y*a2.y + a3.x*a3.x + a3.y*a3.y;
    s = blockSum(s);
    float inv = 1.0f / fmaxf(sqrtf(s), 1e-12f);
    long eb = row * 512;
    // u0 = channels (4t+0,4t+1),(4t+2,4t+3) -> E[2t]=a0.x, O[2t]=a0.y, E[2t+1]=a1.x, O[2t+1]=a1.y
    Eh[eb + t]       = packh(a0.x * inv, a1.x * inv);
    Oh[eb + t]       = packh(a0.y * inv, a1.y * inv);
    Eh[eb + t + 256] = packh(a2.x * inv, a3.x * inv);
    Oh[eb + t + 256] = packh(a2.y * inv, a3.y * inv);
}

// normalize fp16 Zl rows over D=256, write fp16 hi
__global__ void __launch_bounds__(128)
k_norm_rows(const uint32_t* __restrict__ Z, uint32_t* __restrict__ Zh)
{
    long row = blockIdx.x;
    int t = threadIdx.x;
    uint32_t u = Z[row * 128 + t];
    float2 v = __half22float2(*(__half2*)&u);
    float s = blockSum(v.x * v.x + v.y * v.y);
    float inv = 1.0f / fmaxf(sqrtf(s), 1e-12f);
    Zh[row * 128 + t] = packh(v.x * inv, v.y * inv);
}

// transpose lat hi [b,256,1024] -> latT hi [b,1024,256]
__global__ void __launch_bounds__(256)
k_transpose(const uint32_t* __restrict__ sH, uint32_t* __restrict__ dH)
{
    __shared__ unsigned short tile[32][34];
    const int b = blockIdx.z, h0 = blockIdx.x * 32, d0 = blockIdx.y * 32;
    const int t = threadIdx.x;
    #pragma unroll
    for (int i = 0; i < 2; i++){
        int s = t + i * 256;
        int d = s >> 4, hu = s & 15;
        uint32_t v = sH[(long)(b * 256 + d0 + d) * 512 + (h0 >> 1) + hu];
        tile[d][2 * hu]     = (unsigned short)(v & 0xFFFFu);
        tile[d][2 * hu + 1] = (unsigned short)(v >> 16);
    }
    __syncthreads();
    #pragma unroll
    for (int i = 0; i < 2; i++){
        int s = t + i * 256;
        int h = s >> 4, du = s & 15;
        uint32_t v = (uint32_t)tile[2 * du][h] | ((uint32_t)tile[2 * du + 1][h] << 16);
        dH[(long)(b * 1024 + h0 + h) * 128 + (d0 >> 1) + du] = v;
    }
}

// latent row inverse norms from fp16 hi
__global__ void __launch_bounds__(256)
k_latnorm(const uint32_t* __restrict__ H, float* __restrict__ R)
{
    long row = blockIdx.x;
    long base = row * 512;
    int t = threadIdx.x;
    float s = 0.0f;
    #pragma unroll
    for (int i = 0; i < 2; i++){
        uint32_t uh = H[base + t + i * 256];
        float2 fh = __half22float2(*(__half2*)&uh);
        s += fh.x * fh.x + fh.y * fh.y;
    }
    s = blockSum(s);
    if (t == 0) R[row] = 1.0f / fmaxf(sqrtf(s), 1e-12f);
}

__global__ void __launch_bounds__(256)
k_softmax(const float* __restrict__ G, const float* __restrict__ R,
          uint32_t* __restrict__ Gh)
{
    long row = blockIdx.x;
    long bb = row >> 8;
    int t = threadIdx.x;
    float ri = R[row];
    float re = R[(bb << 8) + t];
    float x = G[row * 256 + t] * ri * re;
    float mx = blockMax(x);
    float p = expf(x - mx);
    float sm = blockSum(p);
    float g = p / sm;
    float gn = __shfl_down_sync(0xffffffffu, g, 1);
    if ((t & 1) == 0){
        Gh[row * 128 + (t >> 1)] = packh(g, gn);
    }
}

// ---------------- launch ----------------
extern "C" void kernel_launch(void* const* d_in, const int* in_sizes, int n_in,
                              void* d_out, int out_size)
{
    const float* v2l = (const float*)d_in[0];
    const float* l2v = (const float*)d_in[1];
    const float* wv  = (const float*)d_in[2];
    const float* gv  = (const float*)d_in[3];
    const float* bv  = (const float*)d_in[4];
    const float* wl  = (const float*)d_in[5];
    const float* gl  = (const float*)d_in[6];
    const float* bl  = (const float*)d_in[7];
    float* out = (float*)d_out;

    float *G, *invr;
    __half *v2lh, *l2vh, *wvh, *wlh, *Yvh, *Zlh;
    __half *Eh, *Oh, *Zh, *lath, *latTh, *Ghb, *l2Th;
    cudaGetSymbolAddress((void**)&G, d_G);
    cudaGetSymbolAddress((void**)&invr, d_invr);
    cudaGetSymbolAddress((void**)&v2lh, g_v2lh);
    cudaGetSymbolAddress((void**)&l2vh, g_l2vh);
    cudaGetSymbolAddress((void**)&wvh, g_wvh);
    cudaGetSymbolAddress((void**)&wlh, g_wlh);
    cudaGetSymbolAddress((void**)&Yvh, g_Yvh);
    cudaGetSymbolAddress((void**)&Zlh, g_Zlh);
    cudaGetSymbolAddress((void**)&Eh, g_Eh);
    cudaGetSymbolAddress((void**)&Oh, g_Oh);
    cudaGetSymbolAddress((void**)&Zh, g_Zh);
    cudaGetSymbolAddress((void**)&lath, g_lath);
    cudaGetSymbolAddress((void**)&latTh, g_latTh);
    cudaGetSymbolAddress((void**)&Ghb, g_Gh);
    cudaGetSymbolAddress((void**)&l2Th, g_l2Th);

    cudaFuncSetAttribute(mma_gemm<8,1,0>, cudaFuncAttributeMaxDynamicSharedMemorySize, SMEM_T0);
    cudaFuncSetAttribute(mma_gemm<9,1,0>, cudaFuncAttributeMaxDynamicSharedMemorySize, SMEM_T0);
    cudaFuncSetAttribute(mma_gemm<7,2,0>, cudaFuncAttributeMaxDynamicSharedMemorySize, SMEM_T0);
    cudaFuncSetAttribute(mma_gemm<0,1,0>, cudaFuncAttributeMaxDynamicSharedMemorySize, SMEM_T0);
    cudaFuncSetAttribute(mma_gemm<7,1,0>, cudaFuncAttributeMaxDynamicSharedMemorySize, SMEM_T0);

    const long FEAT = (long)CCH * HWD;
    dim3 blk(256);

    // 0) splits (hi only)
    k_split<<<8192, blk>>>((const float4*)v2l, (uint2*)v2lh, (int)(BATCH*FEAT/4));
    k_split<<<8192, blk>>>((const float4*)l2v, (uint2*)l2vh, (int)(BATCH*FEAT/4));
    k_split<<<256, blk>>>((const float4*)wv, (uint2*)wvh, DD*HWD/4);
    k_split<<<256, blk>>>((const float4*)wl, (uint2*)wlh, DD*HWD/4);

    // 1) Yvh = relu(bn(Wv . V^T)) fp16 out  (1-pass)
    {
        GArgs a = { wvh, nullptr, v2lh, nullptr, nullptr, nullptr,
                    Yvh, nullptr, gv, bv, 0, FEAT, (long)DD*CCH, HWD, HWD, CCH, HWD };
        mma_gemm<8,1,0><<<dim3(CCH/128, DD/128, BATCH), blk, SMEM_T0>>>(a);
    }
    // 2) Zlh = relu(bn(Xl . Wl^T)) fp16 out  (1-pass)
    {
        GArgs a = { l2vh, nullptr, wlh, nullptr, nullptr, nullptr,
                    Zlh, nullptr, gl, bl, FEAT, 0, (long)CCH*DD, HWD, HWD, DD, HWD };
        mma_gemm<9,1,0><<<dim3(DD/128, CCH/128, BATCH), blk, SMEM_T0>>>(a);
    }
    // 3) norm Yvh rows -> E/O hi
    k_norm_v2l<<<BATCH*DD, blk>>>((const uint2*)Yvh, (uint32_t*)Eh, (uint32_t*)Oh);
    // 4) norm Zlh rows -> Zh hi
    k_norm_rows<<<BATCH*CCH, 128>>>((const uint32_t*)Zlh, (uint32_t*)Zh);
    // 5) lat = E.Vlow^T + O.Vhigh^T  (1-pass) -> fp16 hi
    {
        GArgs a = { Eh, nullptr, v2lh, Oh, nullptr, v2lh + (long)HWD*HWD,
                    lath, nullptr, nullptr, nullptr,
                    (long)DD*HWD, FEAT, (long)DD*HWD, HWD, HWD, HWD, HWD };
        mma_gemm<7,2,0><<<dim3(HWD/128, DD/128, BATCH), blk, SMEM_T0>>>(a);
    }
    // 6) transpose lat hi -> latT hi
    k_transpose<<<dim3(32, 8, BATCH), blk>>>((const uint32_t*)lath, (uint32_t*)latTh);
    // 7) latent row inverse norms (hi)
    k_latnorm<<<BATCH*DD, blk>>>((const uint32_t*)lath, invr);
    // 8) G = lat . lat^T  (1-pass, fp32)
    {
        GArgs a = { lath, nullptr, lath, nullptr, nullptr, nullptr,
                    G, nullptr, nullptr, nullptr,
                    (long)DD*HWD, (long)DD*HWD, (long)DD*DD, HWD, HWD, DD, HWD };
        mma_gemm<0,1,0><<<dim3(DD/128, DD/128, BATCH), blk, SMEM_T0>>>(a);
    }
    // 9) aff = softmax(G * invr_d * invr_e) -> fp16 hi
    k_softmax<<<BATCH*DD, blk>>>(G, invr, (uint32_t*)Ghb);
    // 10) l2T = latT . aff^T  (1-pass) -> fp16 hi
    {
        GArgs a = { latTh, nullptr, Ghb, nullptr, nullptr, nullptr,
                    l2Th, nullptr, nullptr, nullptr,
                    (long)HWD*DD, (long)DD*DD, (long)HWD*DD, DD, DD, DD, DD };
        mma_gemm<7,1,0><<<dim3(DD/128, HWD/128, BATCH), blk, SMEM_T0>>>(a);
    }
    // 11) out = Zl_adj . l2T^T  (1-pass, fp32)
    {
        GArgs a = { Zh, nullptr, l2Th, nullptr, nullptr, nullptr,
                    out, nullptr, nullptr, nullptr,
                    (long)CCH*DD, (long)HWD*DD, (long)CCH*HWD, DD, DD, HWD, DD };
        mma_gemm<0,1,0><<<dim3(HWD/128, CCH/128, BATCH), blk, SMEM_T0>>>(a);
    }
}

// round 16
// speedup vs baseline: 2.1073x; 1.0349x over previous
#include <cuda_runtime.h>
#include <cuda_fp16.h>
#include <math.h>
#include <stdint.h>

#define BATCH 16
#define CCH   2048
#define HWD   1024
#define DD    256
#define BN_RS 0.9999950000374997f   // 1/sqrt(1 + 1e-5)

// ---------------- scratch (device globals; no allocation) ----------------
__device__ __align__(16) float d_G  [BATCH * DD * DD];
__device__ float d_invr[BATCH * DD];

__device__ __align__(16) __half g_v2lh[BATCH*CCH*HWD];
__device__ __align__(16) __half g_l2vh[BATCH*CCH*HWD];
__device__ __align__(16) __half g_wvh[DD*HWD];
__device__ __align__(16) __half g_wlh[DD*HWD];
__device__ __align__(16) __half g_Yvh[BATCH*DD*CCH];
__device__ __align__(16) __half g_Zlh[BATCH*CCH*DD];
__device__ __align__(16) __half g_Eh[BATCH*DD*HWD];
__device__ __align__(16) __half g_Oh[BATCH*DD*HWD];
__device__ __align__(16) __half g_Zh[BATCH*CCH*DD];
__device__ __align__(16) __half g_lath[BATCH*DD*HWD];
__device__ __align__(16) __half g_latTh[BATCH*HWD*DD];
__device__ __align__(16) __half g_Gh[BATCH*DD*DD];
__device__ __align__(16) __half g_l2Th[BATCH*HWD*DD];

// ---------------- helpers ----------------
__device__ __forceinline__ uint32_t cvta_s(const void* p){
    return (uint32_t)__cvta_generic_to_shared(p);
}
__device__ __forceinline__ void cpa16(uint32_t d, const void* s){
    asm volatile("cp.async.cg.shared.global [%0], [%1], 16;" :: "r"(d), "l"(s));
}
#define CP_COMMIT() asm volatile("cp.async.commit_group;")
#define CP_WAIT1()  asm volatile("cp.async.wait_group 1;")

#define LDSM4(R, addr) \
    asm volatile("ldmatrix.sync.aligned.m8n8.x4.shared.b16 {%0,%1,%2,%3}, [%4];" \
        : "=r"((R)[0]), "=r"((R)[1]), "=r"((R)[2]), "=r"((R)[3]) : "r"(addr))

#define MMA16816(d, A, b0, b1) \
    asm volatile("mma.sync.aligned.m16n8k16.row.col.f32.f16.f16.f32 " \
        "{%0,%1,%2,%3}, {%4,%5,%6,%7}, {%8,%9}, {%0,%1,%2,%3};" \
        : "+f"((d)[0]), "+f"((d)[1]), "+f"((d)[2]), "+f"((d)[3]) \
        : "r"((A)[0]), "r"((A)[1]), "r"((A)[2]), "r"((A)[3]), "r"(b0), "r"(b1))

__device__ __forceinline__ uint32_t packh(float x, float y){
    __half2 h = __floats2half2_rn(x, y);
    return *(uint32_t*)&h;
}
__device__ __forceinline__ void split16h(float4 v, uint2& hi){
    hi.x = packh(v.x, v.y); hi.y = packh(v.z, v.w);
}

// ---------------- fp16 NT GEMM, 64-K stages (2 sub-tiles), 3-ring, 2 CTA/SM
// D[m,n] = sum_p sum_k A_p[m,k]*B_p[n,k]
// EPI: 0 fp32; 7 fp16; 8 BN+ReLU row -> fp16; 9 BN+ReLU col -> fp16
struct GArgs {
    const __half *A0, *B0, *A1, *B1;
    void *C;
    const float *gs, *bs;
    long sA, sB, sC;
    int lda, ldb, ldc, K;
};

// stage 32KB = [A0 8K | B0 8K | A1 8K | B1 8K]; rows 64B, q = ch ^ ((row>>1)&3)
#define STG64  32768
#define G_SMEM (3 * STG64)

template<int EPI, int NP>
__global__ void __launch_bounds__(256, 2) mma_gemm(GArgs a)
{
    extern __shared__ __align__(128) char smem[];
    const int tid = threadIdx.x, w = tid >> 5, lane = tid & 31;
    const int bn0 = blockIdx.x << 7, bm0 = blockIdx.y << 7, b = blockIdx.z;
    const int KS = a.K >> 6;          // 64-K stages per operand
    const int NS = KS * NP;
    const uint32_t sbase = cvta_s(smem);
    const int wm = w >> 2, wn = w & 3;

    const int r0 = tid >> 2, ch = tid & 3;
    const uint32_t q16 = (uint32_t)((ch ^ ((r0 >> 1) & 3)) * 16);

    auto issue = [&](int s){
        if (s >= NS) return;
        int p = (NP == 2 && s >= KS) ? 1 : 0;
        long kbase = (long)(s - p * KS) * 64;
        const __half* Ab = (p ? a.A1 : a.A0) + (long)b * a.sA + (long)bm0 * a.lda;
        const __half* Bb = (p ? a.B1 : a.B0) + (long)b * a.sB + (long)bn0 * a.ldb;
        uint32_t dst0 = sbase + (uint32_t)(s % 3) * STG64 + (uint32_t)r0 * 64u + q16;
        #pragma unroll
        for (int sub = 0; sub < 2; sub++){
            long k0 = kbase + sub * 32;
            const __half* ap = Ab + (long)r0 * a.lda + k0 + ch * 8;
            cpa16(dst0 + sub * 16384,        ap);
            cpa16(dst0 + sub * 16384 + 4096, ap + 64 * a.lda);
            const __half* bp = Bb + (long)r0 * a.ldb + k0 + ch * 8;
            cpa16(dst0 + sub * 16384 + 8192,        bp);
            cpa16(dst0 + sub * 16384 + 8192 + 4096, bp + 64 * a.ldb);
        }
    };

    float acc[4][4][4];
    #pragma unroll
    for (int i = 0; i < 4; i++)
        #pragma unroll
        for (int j = 0; j < 4; j++)
            #pragma unroll
            for (int t = 0; t < 4; t++) acc[i][j][t] = 0.0f;

    const int aRow = wm * 64 + (lane & 15);
    const uint32_t lqA = (uint32_t)(((lane & 15) >> 1) & 3);
    const uint32_t aC0 = (uint32_t)(lane >> 4);
    const int bRow = wn * 32 + (lane & 7) + ((lane >> 4) & 1) * 8;
    const uint32_t lqB = (uint32_t)(((lane & 7) >> 1) & 3);
    const uint32_t bC0 = (uint32_t)((lane >> 3) & 1);

    issue(0); CP_COMMIT();
    issue(1); CP_COMMIT();

    for (int i = 0; i < NS; i++){
        CP_WAIT1();
        __syncthreads();
        issue(i + 2);            // buffer (i+2)%3 == (i-1)%3, free past the barrier
        CP_COMMIT();

        const uint32_t stb = sbase + (uint32_t)(i % 3) * STG64;
        #pragma unroll
        for (int sub = 0; sub < 2; sub++){
            const uint32_t sb = stb + (uint32_t)sub * 16384u;
            #pragma unroll
            for (int ks = 0; ks < 2; ks++){
                const uint32_t qa = ((aC0 + 2 * ks) ^ lqA) * 16u;
                const uint32_t qb = ((bC0 + 2 * ks) ^ lqB) * 16u;
                uint32_t Afh[4][4], Bfh[2][4];
                #pragma unroll
                for (int mi = 0; mi < 4; mi++){
                    uint32_t ad = sb + (uint32_t)(aRow + mi * 16) * 64u + qa;
                    LDSM4(Afh[mi], ad);
                }
                #pragma unroll
                for (int nb = 0; nb < 2; nb++){
                    uint32_t bd = sb + 8192u + (uint32_t)(bRow + nb * 16) * 64u + qb;
                    LDSM4(Bfh[nb], bd);
                }
                #pragma unroll
                for (int mi = 0; mi < 4; mi++)
                    #pragma unroll
                    for (int ni = 0; ni < 4; ni++){
                        int nb = ni >> 1, h = (ni & 1) * 2;
                        MMA16816(acc[mi][ni], Afh[mi], Bfh[nb][h], Bfh[nb][h + 1]);
                    }
            }
        }
    }

    // ---- epilogue
    const int r1 = lane >> 2, cq = (lane & 3) * 2;
    if (EPI == 7 || EPI == 8 || EPI == 9){
        __half* Ch = (__half*)a.C;
        const long cb = (long)b * a.sC;
        #pragma unroll
        for (int mi = 0; mi < 4; mi++){
            int m0 = bm0 + wm * 64 + mi * 16 + r1;
            float s0 = 0.f, b0_ = 0.f, s1 = 0.f, b1_ = 0.f;
            if (EPI == 8){
                s0 = a.gs[m0] * BN_RS;     b0_ = a.bs[m0];
                s1 = a.gs[m0 + 8] * BN_RS; b1_ = a.bs[m0 + 8];
            }
            #pragma unroll
            for (int ni = 0; ni < 4; ni++){
                int n = bn0 + wn * 32 + ni * 8 + cq;
                float v0 = acc[mi][ni][0], v1 = acc[mi][ni][1];
                float v2 = acc[mi][ni][2], v3 = acc[mi][ni][3];
                if (EPI == 8){
                    v0 = fmaxf(fmaf(v0, s0, b0_), 0.f); v1 = fmaxf(fmaf(v1, s0, b0_), 0.f);
                    v2 = fmaxf(fmaf(v2, s1, b1_), 0.f); v3 = fmaxf(fmaf(v3, s1, b1_), 0.f);
                } else if (EPI == 9){
                    float gs0 = a.gs[n] * BN_RS, bb0 = a.bs[n];
                    float gs1 = a.gs[n + 1] * BN_RS, bb1 = a.bs[n + 1];
                    v0 = fmaxf(fmaf(v0, gs0, bb0), 0.f); v1 = fmaxf(fmaf(v1, gs1, bb1), 0.f);
                    v2 = fmaxf(fmaf(v2, gs0, bb0), 0.f); v3 = fmaxf(fmaf(v3, gs1, bb1), 0.f);
                }
                *(uint32_t*)(Ch + cb + (long)m0 * a.ldc + n)       = packh(v0, v1);
                *(uint32_t*)(Ch + cb + (long)(m0 + 8) * a.ldc + n) = packh(v2, v3);
            }
        }
    } else {
        float* Cb = (float*)a.C + (long)b * a.sC;
        #pragma unroll
        for (int mi = 0; mi < 4; mi++){
            int m0 = bm0 + wm * 64 + mi * 16 + r1;
            #pragma unroll
            for (int ni = 0; ni < 4; ni++){
                int n = bn0 + wn * 32 + ni * 8 + cq;
                *(float2*)(Cb + (long)m0 * a.ldc + n)
                    = make_float2(acc[mi][ni][0], acc[mi][ni][1]);
                *(float2*)(Cb + (long)(m0 + 8) * a.ldc + n)
                    = make_float2(acc[mi][ni][2], acc[mi][ni][3]);
            }
        }
    }
}

// ---------------- reductions ----------------
__device__ __forceinline__ float warpSum(float v){
    #pragma unroll
    for (int o = 16; o; o >>= 1) v += __shfl_xor_sync(0xffffffffu, v, o);
    return v;
}
__device__ __forceinline__ float warpMax(float v){
    #pragma unroll
    for (int o = 16; o; o >>= 1) v = fmaxf(v, __shfl_xor_sync(0xffffffffu, v, o));
    return v;
}
__device__ __forceinline__ float blockSum(float v){
    __shared__ float sh[32];
    int w = threadIdx.x >> 5, l = threadIdx.x & 31;
    v = warpSum(v);
    if (l == 0) sh[w] = v;
    __syncthreads();
    int nw = blockDim.x >> 5;
    if (w == 0){ float x = (l < nw) ? sh[l] : 0.0f; x = warpSum(x); if (l == 0) sh[0] = x; }
    __syncthreads();
    float r = sh[0];
    __syncthreads();
    return r;
}
__device__ __forceinline__ float blockMax(float v){
    __shared__ float sh[32];
    int w = threadIdx.x >> 5, l = threadIdx.x & 31;
    v = warpMax(v);
    if (l == 0) sh[w] = v;
    __syncthreads();
    int nw = blockDim.x >> 5;
    if (w == 0){ float x = (l < nw) ? sh[l] : -INFINITY; x = warpMax(x); if (l == 0) sh[0] = x; }
    __syncthreads();
    float r = sh[0];
    __syncthreads();
    return r;
}

// ---------------- elementwise kernels ----------------
// merged split of both big inputs (hi only)
__global__ void __launch_bounds__(256)
k_split_big(const float4* __restrict__ in1, uint2* __restrict__ hi1,
            const float4* __restrict__ in2, uint2* __restrict__ hi2, int n4)
{
    int i = blockIdx.x * blockDim.x + threadIdx.x;
    int stride = gridDim.x * blockDim.x;
    int total = 2 * n4;
    for (; i < total; i += stride){
        const float4* in = (i < n4) ? in1 : in2;
        uint2* hi = (i < n4) ? hi1 : hi2;
        int j = (i < n4) ? i : i - n4;
        uint2 h;
        split16h(in[j], h);
        hi[j] = h;
    }
}
__global__ void __launch_bounds__(256)
k_split_w(const float4* __restrict__ in1, uint2* __restrict__ hi1,
          const float4* __restrict__ in2, uint2* __restrict__ hi2, int n4)
{
    int i = blockIdx.x * blockDim.x + threadIdx.x;
    int stride = gridDim.x * blockDim.x;
    int total = 2 * n4;
    for (; i < total; i += stride){
        const float4* in = (i < n4) ? in1 : in2;
        uint2* hi = (i < n4) ? hi1 : hi2;
        int j = (i < n4) ? i : i - n4;
        uint2 h;
        split16h(in[j], h);
        hi[j] = h;
    }
}

// normalize fp16 Yv rows over C=2048, deinterleave even/odd, write fp16 hi
__global__ void __launch_bounds__(256)
k_norm_v2l(const uint2* __restrict__ Y,
           uint32_t* __restrict__ Eh, uint32_t* __restrict__ Oh)
{
    long row = blockIdx.x;
    const uint2* y = Y + row * 512;
    int t = threadIdx.x;
    uint2 u0 = y[t], u1 = y[t + 256];
    float2 a0 = __half22float2(*(__half2*)&u0.x);
    float2 a1 = __half22float2(*(__half2*)&u0.y);
    float2 a2 = __half22float2(*(__half2*)&u1.x);
    float2 a3 = __half22float2(*(__half2*)&u1.y);
    float s = a0.x*a0.x + a0.y*a0.y + a1.x*a1.x + a1.y*a1.y
            + a2.x*a2.x + a2.y*a2.y + a3.x*a3.x + a3.y*a3.y;
    s = blockSum(s);
    float inv = 1.0f / fmaxf(sqrtf(s), 1e-12f);
    long eb = row * 512;
    Eh[eb + t]       = packh(a0.x * inv, a1.x * inv);
    Oh[eb + t]       = packh(a0.y * inv, a1.y * inv);
    Eh[eb + t + 256] = packh(a2.x * inv, a3.x * inv);
    Oh[eb + t + 256] = packh(a2.y * inv, a3.y * inv);
}

// normalize fp16 Zl rows over D=256, write fp16 hi
__global__ void __launch_bounds__(128)
k_norm_rows(const uint32_t* __restrict__ Z, uint32_t* __restrict__ Zh)
{
    long row = blockIdx.x;
    int t = threadIdx.x;
    uint32_t u = Z[row * 128 + t];
    float2 v = __half22float2(*(__half2*)&u);
    float s = blockSum(v.x * v.x + v.y * v.y);
    float inv = 1.0f / fmaxf(sqrtf(s), 1e-12f);
    Zh[row * 128 + t] = packh(v.x * inv, v.y * inv);
}

// transpose lat hi [b,256,1024] -> latT hi [b,1024,256]
__global__ void __launch_bounds__(256)
k_transpose(const uint32_t* __restrict__ sH, uint32_t* __restrict__ dH)
{
    __shared__ unsigned short tile[32][34];
    const int b = blockIdx.z, h0 = blockIdx.x * 32, d0 = blockIdx.y * 32;
    const int t = threadIdx.x;
    #pragma unroll
    for (int i = 0; i < 2; i++){
        int s = t + i * 256;
        int d = s >> 4, hu = s & 15;
        uint32_t v = sH[(long)(b * 256 + d0 + d) * 512 + (h0 >> 1) + hu];
        tile[d][2 * hu]     = (unsigned short)(v & 0xFFFFu);
        tile[d][2 * hu + 1] = (unsigned short)(v >> 16);
    }
    __syncthreads();
    #pragma unroll
    for (int i = 0; i < 2; i++){
        int s = t + i * 256;
        int h = s >> 4, du = s & 15;
        uint32_t v = (uint32_t)tile[2 * du][h] | ((uint32_t)tile[2 * du + 1][h] << 16);
        dH[(long)(b * 1024 + h0 + h) * 128 + (d0 >> 1) + du] = v;
    }
}

// latent row inverse norms from fp16 hi
__global__ void __launch_bounds__(256)
k_latnorm(const uint32_t* __restrict__ H, float* __restrict__ R)
{
    long row = blockIdx.x;
    long base = row * 512;
    int t = threadIdx.x;
    float s = 0.0f;
    #pragma unroll
    for (int i = 0; i < 2; i++){
        uint32_t uh = H[base + t + i * 256];
        float2 fh = __half22float2(*(__half2*)&uh);
        s += fh.x * fh.x + fh.y * fh.y;
    }
    s = blockSum(s);
    if (t == 0) R[row] = 1.0f / fmaxf(sqrtf(s), 1e-12f);
}

__global__ void __launch_bounds__(256)
k_softmax(const float* __restrict__ G, const float* __restrict__ R,
          uint32_t* __restrict__ Gh)
{
    long row = blockIdx.x;
    long bb = row >> 8;
    int t = threadIdx.x;
    float ri = R[row];
    float re = R[(bb << 8) + t];
    float x = G[row * 256 + t] * ri * re;
    float mx = blockMax(x);
    float p = expf(x - mx);
    float sm = blockSum(p);
    float g = p / sm;
    float gn = __shfl_down_sync(0xffffffffu, g, 1);
    if ((t & 1) == 0){
        Gh[row * 128 + (t >> 1)] = packh(g, gn);
    }
}

// ---------------- launch ----------------
extern "C" void kernel_launch(void* const* d_in, const int* in_sizes, int n_in,
                              void* d_out, int out_size)
{
    const float* v2l = (const float*)d_in[0];
    const float* l2v = (const float*)d_in[1];
    const float* wv  = (const float*)d_in[2];
    const float* gv  = (const float*)d_in[3];
    const float* bv  = (const float*)d_in[4];
    const float* wl  = (const float*)d_in[5];
    const float* gl  = (const float*)d_in[6];
    const float* bl  = (const float*)d_in[7];
    float* out = (float*)d_out;

    float *G, *invr;
    __half *v2lh, *l2vh, *wvh, *wlh, *Yvh, *Zlh;
    __half *Eh, *Oh, *Zh, *lath, *latTh, *Ghb, *l2Th;
    cudaGetSymbolAddress((void**)&G, d_G);
    cudaGetSymbolAddress((void**)&invr, d_invr);
    cudaGetSymbolAddress((void**)&v2lh, g_v2lh);
    cudaGetSymbolAddress((void**)&l2vh, g_l2vh);
    cudaGetSymbolAddress((void**)&wvh, g_wvh);
    cudaGetSymbolAddress((void**)&wlh, g_wlh);
    cudaGetSymbolAddress((void**)&Yvh, g_Yvh);
    cudaGetSymbolAddress((void**)&Zlh, g_Zlh);
    cudaGetSymbolAddress((void**)&Eh, g_Eh);
    cudaGetSymbolAddress((void**)&Oh, g_Oh);
    cudaGetSymbolAddress((void**)&Zh, g_Zh);
    cudaGetSymbolAddress((void**)&lath, g_lath);
    cudaGetSymbolAddress((void**)&latTh, g_latTh);
    cudaGetSymbolAddress((void**)&Ghb, g_Gh);
    cudaGetSymbolAddress((void**)&l2Th, g_l2Th);

    cudaFuncSetAttribute(mma_gemm<8,1>, cudaFuncAttributeMaxDynamicSharedMemorySize, G_SMEM);
    cudaFuncSetAttribute(mma_gemm<9,1>, cudaFuncAttributeMaxDynamicSharedMemorySize, G_SMEM);
    cudaFuncSetAttribute(mma_gemm<7,2>, cudaFuncAttributeMaxDynamicSharedMemorySize, G_SMEM);
    cudaFuncSetAttribute(mma_gemm<0,1>, cudaFuncAttributeMaxDynamicSharedMemorySize, G_SMEM);
    cudaFuncSetAttribute(mma_gemm<7,1>, cudaFuncAttributeMaxDynamicSharedMemorySize, G_SMEM);

    const long FEAT = (long)CCH * HWD;
    dim3 blk(256);

    // 0) splits (hi only), merged launches
    k_split_big<<<16384, blk>>>((const float4*)v2l, (uint2*)v2lh,
                                (const float4*)l2v, (uint2*)l2vh, (int)(BATCH*FEAT/4));
    k_split_w<<<512, blk>>>((const float4*)wv, (uint2*)wvh,
                            (const float4*)wl, (uint2*)wlh, DD*HWD/4);

    // 1) Yvh = relu(bn(Wv . V^T)) fp16
    {
        GArgs a = { wvh, v2lh, nullptr, nullptr,
                    Yvh, gv, bv, 0, FEAT, (long)DD*CCH, HWD, HWD, CCH, HWD };
        mma_gemm<8,1><<<dim3(CCH/128, DD/128, BATCH), blk, G_SMEM>>>(a);
    }
    // 2) Zlh = relu(bn(Xl . Wl^T)) fp16
    {
        GArgs a = { l2vh, wlh, nullptr, nullptr,
                    Zlh, gl, bl, FEAT, 0, (long)CCH*DD, HWD, HWD, DD, HWD };
        mma_gemm<9,1><<<dim3(DD/128, CCH/128, BATCH), blk, G_SMEM>>>(a);
    }
    // 3) norm Yvh rows -> E/O hi
    k_norm_v2l<<<BATCH*DD, blk>>>((const uint2*)Yvh, (uint32_t*)Eh, (uint32_t*)Oh);
    // 4) norm Zlh rows -> Zh hi
    k_norm_rows<<<BATCH*CCH, 128>>>((const uint32_t*)Zlh, (uint32_t*)Zh);
    // 5) lat = E.Vlow^T + O.Vhigh^T -> fp16 hi
    {
        GArgs a = { Eh, v2lh, Oh, v2lh + (long)HWD*HWD,
                    lath, nullptr, nullptr,
                    (long)DD*HWD, FEAT, (long)DD*HWD, HWD, HWD, HWD, HWD };
        mma_gemm<7,2><<<dim3(HWD/128, DD/128, BATCH), blk, G_SMEM>>>(a);
    }
    // 6) transpose lat hi -> latT hi
    k_transpose<<<dim3(32, 8, BATCH), blk>>>((const uint32_t*)lath, (uint32_t*)latTh);
    // 7) latent row inverse norms
    k_latnorm<<<BATCH*DD, blk>>>((const uint32_t*)lath, invr);
    // 8) G = lat . lat^T (fp32)
    {
        GArgs a = { lath, lath, nullptr, nullptr,
                    G, nullptr, nullptr,
                    (long)DD*HWD, (long)DD*HWD, (long)DD*DD, HWD, HWD, DD, HWD };
        mma_gemm<0,1><<<dim3(DD/128, DD/128, BATCH), blk, G_SMEM>>>(a);
    }
    // 9) aff = softmax(G * invr_d * invr_e) -> fp16 hi
    k_softmax<<<BATCH*DD, blk>>>(G, invr, (uint32_t*)Ghb);
    // 10) l2T = latT . aff^T -> fp16 hi
    {
        GArgs a = { latTh, Ghb, nullptr, nullptr,
                    l2Th, nullptr, nullptr,
                    (long)HWD*DD, (long)DD*DD, (long)HWD*DD, DD, DD, DD, DD };
        mma_gemm<7,1><<<dim3(DD/128, HWD/128, BATCH), blk, G_SMEM>>>(a);
    }
    // 11) out = Zl_adj . l2T^T (fp32)
    {
        GArgs a = { Zh, l2Th, nullptr, nullptr,
                    out, nullptr, nullptr,
                    (long)CCH*DD, (long)HWD*DD, (long)CCH*HWD, DD, DD, HWD, DD };
        mma_gemm<0,1><<<dim3(HWD/128, CCH/128, BATCH), blk, G_SMEM>>>(a);
    }
}